// round 6
// baseline (speedup 1.0000x reference)
#include <cuda_runtime.h>
#include <cuda_bf16.h>
#include <cstdint>

typedef unsigned int u32;
typedef unsigned long long u64;
typedef __nv_bfloat16 bf16;

#define NN 2048
#define NE 6144
#define KDV 128
#define DVO 64
#define DEI 16
#define DEO 16

// =====================  scratch  =====================
__device__ __align__(16) bf16 g_m1A_hi[NN * NE];
__device__ __align__(16) bf16 g_m1A_lo[NN * NE];
__device__ __align__(16) bf16 g_m1B_hi[NN * NE];
__device__ __align__(16) bf16 g_m1B_lo[NN * NE];
__device__ __align__(16) bf16 g_m2A_hi[NE * NN];
__device__ __align__(16) bf16 g_m2A_lo[NE * NN];
__device__ __align__(16) bf16 g_m2B_hi[NE * NN];
__device__ __align__(16) bf16 g_m2B_lo[NE * NN];
__device__ __align__(16) float g_adjAv[NN * NN];
__device__ __align__(16) float g_adjAe[(size_t)NE * NE];
__device__ __align__(16) float g_HW[NN * DVO];
__device__ __align__(16) float g_HeW[NE * DEO];
__device__ __align__(16) float g_HeWs[NE * DEO];
__device__ __align__(16) float g_de[NE];
__device__ __align__(16) float g_dv[NN];
__device__ u32 g_cmaxu[NE];

// =====================  helpers  =====================
__device__ __forceinline__ u32 smem_u32(const void* p) {
    u32 a;
    asm("{ .reg .u64 t; cvta.to.shared.u64 t, %1; cvt.u32.u64 %0, t; }" : "=r"(a) : "l"(p));
    return a;
}

__device__ __forceinline__ void cp16(u32 saddr, const bf16* gptr) {
    asm volatile("cp.async.cg.shared.global [%0], [%1], 16;"
                 :: "r"(saddr), "l"(__cvta_generic_to_global(gptr)) : "memory");
}

#define LDSM4(r, addr)                                                          \
    asm volatile("ldmatrix.sync.aligned.m8n8.x4.shared.b16 {%0,%1,%2,%3}, [%4];" \
                 : "=r"((r)[0]), "=r"((r)[1]), "=r"((r)[2]), "=r"((r)[3]) : "r"(addr))

#define MMA_BF16(d, a, b)                                                        \
    asm volatile("mma.sync.aligned.m16n8k16.row.col.f32.bf16.bf16.f32 "          \
                 "{%0,%1,%2,%3},{%4,%5,%6,%7},{%8,%9},{%0,%1,%2,%3};"            \
                 : "+f"((d)[0]), "+f"((d)[1]), "+f"((d)[2]), "+f"((d)[3])        \
                 : "r"((a)[0]), "r"((a)[1]), "r"((a)[2]), "r"((a)[3]),           \
                   "r"((b)[0]), "r"((b)[1]))

__device__ __forceinline__ void bsplit(float x, bf16& hi, bf16& lo) {
    hi = __float2bfloat16_rn(x);
    lo = __float2bfloat16_rn(x - __bfloat162float(hi));
}
__device__ __forceinline__ u32 pkb2(bf16 a, bf16 b) {
    __nv_bfloat162 h = __halves2bfloat162(a, b);
    return *(u32*)&h;
}
__device__ __forceinline__ u32 fkey(float f) {
    u32 b = __float_as_uint(f);
    return (b & 0x80000000u) ? ~b : (b | 0x80000000u);
}

// =====================  tiny prologue kernels  =====================
__global__ void k_de(const float* __restrict__ He, const float* __restrict__ pv) {
    int e = blockIdx.x * 256 + threadIdx.x;
    float s = 0.f;
#pragma unroll
    for (int k = 0; k < DEI; k++) s += He[e * DEI + k] * pv[k];
    g_de[e] = s;
}

__global__ void k_hew(const float* __restrict__ He, const float* __restrict__ We) {
    int idx = blockIdx.x * 256 + threadIdx.x;
    int e = idx >> 4, c = idx & 15;
    float s = 0.f;
#pragma unroll
    for (int k = 0; k < DEI; k++) s += He[e * DEI + k] * We[k * DEO + c];
    g_HeW[idx] = s;
}

__global__ void k_hw(const float* __restrict__ Hv, const float* __restrict__ Wv) {
    int idx = blockIdx.x * 256 + threadIdx.x;
    int i = idx >> 6, c = idx & 63;
    float s = 0.f;
#pragma unroll 8
    for (int k = 0; k < KDV; k++) s += Hv[i * KDV + k] * Wv[k * DVO + c];
    g_HW[idx] = s;
}

__global__ void k_cinit() {
    g_cmaxu[blockIdx.x * 256 + threadIdx.x] = 0u;
}

// mult1 prep: B = T (hi/lo), A = T * d_e[col] (hi/lo). [NN][NE] K-major, bf16.
__global__ void k_split1(const float* __restrict__ T) {
    size_t i = (size_t)blockIdx.x * 256 + threadIdx.x;   // float4 index
    float4 t = ((const float4*)T)[i];
    int col = (int)((i * 4) % NE);
    float4 de = *(const float4*)(g_de + col);
    bf16 hx, lx, hy, ly, hz, lz, hw, lw;
    bsplit(t.x, hx, lx); bsplit(t.y, hy, ly); bsplit(t.z, hz, lz); bsplit(t.w, hw, lw);
    ((uint2*)g_m1B_hi)[i] = make_uint2(pkb2(hx, hy), pkb2(hz, hw));
    ((uint2*)g_m1B_lo)[i] = make_uint2(pkb2(lx, ly), pkb2(lz, lw));
    float ax = t.x * de.x, ay = t.y * de.y, az = t.z * de.z, aw = t.w * de.w;
    bsplit(ax, hx, lx); bsplit(ay, hy, ly); bsplit(az, hz, lz); bsplit(aw, hw, lw);
    ((uint2*)g_m1A_hi)[i] = make_uint2(pkb2(hx, hy), pkb2(hz, hw));
    ((uint2*)g_m1A_lo)[i] = make_uint2(pkb2(lx, ly), pkb2(lz, lw));
}

// mult2 prep (transpose): B2[m][k] = T[k][m]; A2[m][k] = T[k][m]*d_v[k]. [NE][NN] bf16.
__global__ void k_split2(const float* __restrict__ T) {
    __shared__ float tile[64][33];
    const int m0 = blockIdx.x * 32, k0 = blockIdx.y * 64;
    const int tx = threadIdx.x, ty = threadIdx.y;     // (32, 8)
#pragma unroll
    for (int j = 0; j < 8; j++) {
        int r = ty + j * 8;
        tile[r][tx] = T[(size_t)(k0 + r) * NE + m0 + tx];
    }
    __syncthreads();
    const int lane = tx, w = ty;
    float2 dv = ((const float2*)(g_dv + k0))[lane];
#pragma unroll
    for (int q = 0; q < 4; q++) {
        const int mloc = w + 8 * q;
        const int m = m0 + mloc;
        float v0 = tile[2 * lane][mloc];
        float v1 = tile[2 * lane + 1][mloc];
        const size_t ob = ((size_t)m * NN + k0) >> 1;   // u32 index
        bf16 h0, l0, h1, l1;
        bsplit(v0, h0, l0); bsplit(v1, h1, l1);
        ((u32*)g_m2B_hi)[ob + lane] = pkb2(h0, h1);
        ((u32*)g_m2B_lo)[ob + lane] = pkb2(l0, l1);
        bsplit(v0 * dv.x, h0, l0); bsplit(v1 * dv.y, h1, l1);
        ((u32*)g_m2A_hi)[ob + lane] = pkb2(h0, h1);
        ((u32*)g_m2A_lo)[ob + lane] = pkb2(l0, l1);
    }
}

// =====================  bf16 3-term tensor-core GEMM + fused epilogue  =====================
// CTA tile 128x128, 4 warps (2x2), warp tile 64x64, KB=32, 3-stage cp.async, 2 CTAs/SM.
#define KB 32
#define STG_BYTES 32768          // Ahi 8K | Alo 8K | Bhi 8K | Blo 8K
#define NSTAGE 3
#define SMEM_DYN (NSTAGE * STG_BYTES)

__device__ __forceinline__ void stage_load(u32 st0, int s,
        const bf16* __restrict__ Ahi, const bf16* __restrict__ Alo,
        const bf16* __restrict__ Bhi, const bf16* __restrict__ Blo,
        int K, int m0, int n0, int k0, int tid) {
    u32 base = st0 + s * STG_BYTES;
#pragma unroll
    for (int i = 0; i < 4; i++) {
        int id = tid + i * 128;                // 0..511
        int r = id >> 2, c = id & 3;           // 128 rows x 4 16B-chunks
        u32 so = (u32)(r * 64 + ((c ^ (r & 3)) << 4));
        size_t gA = (size_t)(m0 + r) * K + k0 + c * 8;
        size_t gB = (size_t)(n0 + r) * K + k0 + c * 8;
        cp16(base + so, Ahi + gA);
        cp16(base + 8192 + so, Alo + gA);
        cp16(base + 16384 + so, Bhi + gB);
        cp16(base + 24576 + so, Blo + gB);
    }
    asm volatile("cp.async.commit_group;" ::: "memory");
}

__global__ __launch_bounds__(128, 2) void k_mult_mma(int which, const float* __restrict__ adj) {
    extern __shared__ char smem[];
    const bf16 *Ahi, *Alo, *Bhi, *Blo;
    float* C;
    int K, ncols;
    if (which == 0) {
        Ahi = g_m1A_hi; Alo = g_m1A_lo; Bhi = g_m1B_hi; Blo = g_m1B_lo;
        C = g_adjAv; K = NE; ncols = NN;
    } else {
        Ahi = g_m2A_hi; Alo = g_m2A_lo; Bhi = g_m2B_hi; Blo = g_m2B_lo;
        C = g_adjAe; K = NN; ncols = NE;
    }
    const u32 st0 = smem_u32(smem);
    const int tid = threadIdx.x;
    const int lane = tid & 31, wid = tid >> 5;
    const int wm = wid >> 1, wn = wid & 1;          // 2 x 2 warp grid, 64x64 tiles
    const int m0 = blockIdx.y * 128, n0 = blockIdx.x * 128;
    const int nk = K / KB;

    float acc[4][8][4];
#pragma unroll
    for (int i = 0; i < 4; i++)
#pragma unroll
        for (int j = 0; j < 8; j++)
#pragma unroll
            for (int q = 0; q < 4; q++) acc[i][j][q] = 0.f;

    stage_load(st0, 0, Ahi, Alo, Bhi, Blo, K, m0, n0, 0, tid);
    stage_load(st0, 1, Ahi, Alo, Bhi, Blo, K, m0, n0, KB, tid);

    const u32 arow = (u32)(wm * 64 + (lane & 15));
    const u32 brow = (u32)(wn * 64 + (lane & 15));
    const u32 asw = arow & 3, bsw = brow & 3;

    for (int kt = 0; kt < nk; kt++) {
        const int s = kt % NSTAGE;
        if (kt + 1 < nk) asm volatile("cp.async.wait_group 1;" ::: "memory");
        else             asm volatile("cp.async.wait_group 0;" ::: "memory");
        __syncthreads();
        if (kt + 2 < nk)
            stage_load(st0, (kt + 2) % NSTAGE, Ahi, Alo, Bhi, Blo, K, m0, n0, (kt + 2) * KB, tid);

        const u32 base = st0 + s * STG_BYTES;
#pragma unroll
        for (int ks = 0; ks < 2; ks++) {
            const u32 cb = (u32)(ks * 2) + (u32)(lane >> 4);
            u32 Bh[8][2], Bl[8][2];
            const u32 boff = base + 16384 + brow * 64 + ((cb ^ bsw) << 4);
#pragma unroll
            for (int nip = 0; nip < 4; nip++) {
                u32 t[4];
                LDSM4(t, boff + nip * 1024);
                Bh[2 * nip][0] = t[0]; Bh[2 * nip][1] = t[2];
                Bh[2 * nip + 1][0] = t[1]; Bh[2 * nip + 1][1] = t[3];
                LDSM4(t, boff + 8192 + nip * 1024);
                Bl[2 * nip][0] = t[0]; Bl[2 * nip][1] = t[2];
                Bl[2 * nip + 1][0] = t[1]; Bl[2 * nip + 1][1] = t[3];
            }
            const u32 aoff = base + arow * 64 + ((cb ^ asw) << 4);
#pragma unroll
            for (int mi = 0; mi < 4; mi++) {
                u32 ah[4], al[4];
                LDSM4(ah, aoff + mi * 1024);
                LDSM4(al, aoff + 8192 + mi * 1024);
#pragma unroll
                for (int ni = 0; ni < 8; ni++) {
                    MMA_BF16(acc[mi][ni], ah, Bh[ni]);
                    MMA_BF16(acc[mi][ni], ah, Bl[ni]);
                    MMA_BF16(acc[mi][ni], al, Bh[ni]);
                }
            }
        }
        __syncthreads();
    }

    // epilogue: diag -> 1, * adj, store; fused column-max (which==1)
    u32 kmax[8][2];
#pragma unroll
    for (int ni = 0; ni < 8; ni++) { kmax[ni][0] = 0u; kmax[ni][1] = 0u; }

#pragma unroll
    for (int mi = 0; mi < 4; mi++) {
#pragma unroll
        for (int h = 0; h < 2; h++) {
            const int row_g = m0 + wm * 64 + mi * 16 + (lane >> 2) + h * 8;
            const size_t rb = (size_t)row_g * ncols;
#pragma unroll
            for (int ni = 0; ni < 8; ni++) {
                const int col_g = n0 + wn * 64 + ni * 8 + (lane & 3) * 2;
                float v0 = acc[mi][ni][h * 2], v1 = acc[mi][ni][h * 2 + 1];
                if (row_g == col_g) v0 = 1.0f;
                if (row_g == col_g + 1) v1 = 1.0f;
                const float2 a = *(const float2*)(adj + rb + col_g);
                v0 *= a.x; v1 *= a.y;
                *(float2*)(C + rb + col_g) = make_float2(v0, v1);
                if (which == 1) {
                    kmax[ni][0] = max(kmax[ni][0], fkey(v0));
                    kmax[ni][1] = max(kmax[ni][1], fkey(v1));
                }
            }
        }
    }
    if (which == 1) {
        u32* scm = (u32*)smem;
        if (tid < 128) scm[tid] = 0u;
        __syncthreads();
#pragma unroll
        for (int ni = 0; ni < 8; ni++) {
            const int cl = wn * 64 + ni * 8 + (lane & 3) * 2;
            atomicMax(scm + cl, kmax[ni][0]);
            atomicMax(scm + cl + 1, kmax[ni][1]);
        }
        __syncthreads();
        if (tid < 128) atomicMax(g_cmaxu + n0 + tid, scm[tid]);
    }
}

// =====================  Hv_out = adjAv @ HW + b_v  =====================
__global__ __launch_bounds__(256) void k_hv(const float* __restrict__ bv, float* __restrict__ out) {
    __shared__ __align__(16) float As[32 * 32];
    __shared__ __align__(16) float Bs[32 * 64];
    const int tid = threadIdx.x;
    const int tx = tid & 15, ty = tid >> 4;
    const int m0 = blockIdx.x * 32;
    const int arow = tid >> 3, ac4 = (tid & 7) * 4;
    const int brow = tid >> 4, bc4 = (tid & 15) * 4;
    float acc[2][4] = {{0, 0, 0, 0}, {0, 0, 0, 0}};
    for (int k0 = 0; k0 < NN; k0 += 32) {
        float4 fa = *(const float4*)(g_adjAv + (m0 + arow) * NN + k0 + ac4);
        float4 fb0 = *(const float4*)(g_HW + (k0 + brow) * DVO + bc4);
        float4 fb1 = *(const float4*)(g_HW + (k0 + brow + 16) * DVO + bc4);
        __syncthreads();
        As[(ac4 + 0) * 32 + arow] = fa.x; As[(ac4 + 1) * 32 + arow] = fa.y;
        As[(ac4 + 2) * 32 + arow] = fa.z; As[(ac4 + 3) * 32 + arow] = fa.w;
        *(float4*)(Bs + brow * 64 + bc4) = fb0;
        *(float4*)(Bs + (brow + 16) * 64 + bc4) = fb1;
        __syncthreads();
#pragma unroll
        for (int kk = 0; kk < 32; kk++) {
            float a0 = As[kk * 32 + ty * 2];
            float a1 = As[kk * 32 + ty * 2 + 1];
            float4 b = *(const float4*)(Bs + kk * 64 + tx * 4);
            acc[0][0] += a0 * b.x; acc[0][1] += a0 * b.y; acc[0][2] += a0 * b.z; acc[0][3] += a0 * b.w;
            acc[1][0] += a1 * b.x; acc[1][1] += a1 * b.y; acc[1][2] += a1 * b.z; acc[1][3] += a1 * b.w;
        }
    }
    float4 bb = *(const float4*)(bv + tx * 4);
#pragma unroll
    for (int r = 0; r < 2; r++) {
        int row = m0 + ty * 2 + r;
        *(float4*)(out + row * DVO + tx * 4) =
            make_float4(acc[r][0] + bb.x, acc[r][1] + bb.y, acc[r][2] + bb.z, acc[r][3] + bb.w);
    }
}

__global__ void k_dv(const float* __restrict__ Hv, const float* __restrict__ pe) {
    int w = (blockIdx.x * blockDim.x + threadIdx.x) >> 5;
    int lane = threadIdx.x & 31;
    float s = Hv[w * DVO + lane] * pe[lane] + Hv[w * DVO + 32 + lane] * pe[32 + lane];
#pragma unroll
    for (int o = 16; o > 0; o >>= 1) s += __shfl_down_sync(0xffffffffu, s, o);
    if (lane == 0) g_dv[w] = s;
}

// finalize colmax from keys, fold 1/(max+1e-10) into HeW -> HeWs
__global__ void k_cmax2() {
    int col = blockIdx.x * 256 + threadIdx.x;
    u32 k = g_cmaxu[col];
    u32 b = (k & 0x80000000u) ? (k ^ 0x80000000u) : ~k;
    float m = __uint_as_float(b);
    float inv = 1.0f / (m + 1e-10f);
#pragma unroll
    for (int c = 0; c < DEO; c++) g_HeWs[col * DEO + c] = g_HeW[col * DEO + c] * inv;
}

__global__ __launch_bounds__(256) void k_he(const float* __restrict__ be, float* __restrict__ out) {
    __shared__ __align__(16) float As[64 * 64];
    __shared__ __align__(16) float Bs[64 * 16];
    const int tid = threadIdx.x;
    const int c = tid & 15, tr = tid >> 4;
    const int m0 = blockIdx.x * 64;
    const int lc4 = (tid & 15) * 4;
    float acc[4] = {0, 0, 0, 0};
    for (int k0 = 0; k0 < NE; k0 += 64) {
        float4 ra[4]; float rb[4];
#pragma unroll
        for (int q = 0; q < 4; q++) {
            int row = tr + q * 16;
            ra[q] = *(const float4*)(g_adjAe + (size_t)(m0 + row) * NE + k0 + lc4);
            rb[q] = g_HeWs[(k0 + row) * DEO + c];
        }
        __syncthreads();
#pragma unroll
        for (int q = 0; q < 4; q++) {
            int row = tr + q * 16;
            *(float4*)(As + row * 64 + lc4) = ra[q];
            Bs[row * 16 + c] = rb[q];
        }
        __syncthreads();
#pragma unroll 8
        for (int kk = 0; kk < 64; kk++) {
            float b = Bs[kk * 16 + c];
            acc[0] += As[(0 * 16 + tr) * 64 + kk] * b;
            acc[1] += As[(1 * 16 + tr) * 64 + kk] * b;
            acc[2] += As[(2 * 16 + tr) * 64 + kk] * b;
            acc[3] += As[(3 * 16 + tr) * 64 + kk] * b;
        }
    }
    float bc = be[c];
#pragma unroll
    for (int q = 0; q < 4; q++)
        out[(m0 + q * 16 + tr) * DEO + c] = acc[q] + bc;
}

// =====================  launch  =====================
extern "C" void kernel_launch(void* const* d_in, const int* in_sizes, int n_in,
                              void* d_out, int out_size) {
    const float* H_v  = (const float*)d_in[0];
    const float* H_e  = (const float*)d_in[1];
    const float* adjv = (const float*)d_in[2];
    const float* adje = (const float*)d_in[3];
    const float* T    = (const float*)d_in[4];
    const float* W_v  = (const float*)d_in[5];
    const float* b_v  = (const float*)d_in[6];
    const float* p_v  = (const float*)d_in[7];
    const float* W_e  = (const float*)d_in[8];
    const float* b_e  = (const float*)d_in[9];
    const float* p_e  = (const float*)d_in[10];
    float* out = (float*)d_out;
    (void)in_sizes; (void)n_in; (void)out_size;

    cudaFuncSetAttribute(k_mult_mma, cudaFuncAttributeMaxDynamicSharedMemorySize, SMEM_DYN);

    k_de<<<24, 256>>>(H_e, p_v);
    k_hew<<<384, 256>>>(H_e, W_e);
    k_hw<<<512, 256>>>(H_v, W_v);
    k_cinit<<<24, 256>>>();
    k_split1<<<12288, 256>>>(T);
    k_mult_mma<<<dim3(16, 16), 128, SMEM_DYN>>>(0, adjv);   // adjAv
    k_hv<<<64, 256>>>(b_v, out);
    k_dv<<<256, 256>>>(out, p_e);
    k_split2<<<dim3(192, 32), dim3(32, 8)>>>(T);
    k_mult_mma<<<dim3(48, 48), 128, SMEM_DYN>>>(1, adje);   // adjAe + fused colmax
    k_cmax2<<<24, 256>>>();
    k_he<<<96, 256>>>(b_e, out + NN * DVO);
}

// round 7
// speedup vs baseline: 1.6189x; 1.6189x over previous
#include <cuda_runtime.h>
#include <cuda_bf16.h>
#include <cstdint>

typedef unsigned int u32;
typedef unsigned long long u64;
typedef __nv_bfloat16 bf16;

#define NN 2048
#define NE 6144
#define KDV 128
#define DVO 64
#define DEI 16
#define DEO 16

// =====================  scratch  =====================
__device__ __align__(16) bf16 g_m1A_hi[NN * NE];
__device__ __align__(16) bf16 g_m1A_lo[NN * NE];
__device__ __align__(16) bf16 g_m1B_hi[NN * NE];
__device__ __align__(16) bf16 g_m1B_lo[NN * NE];
__device__ __align__(16) bf16 g_m2A_hi[NE * NN];
__device__ __align__(16) bf16 g_m2A_lo[NE * NN];
__device__ __align__(16) bf16 g_m2B_hi[NE * NN];
__device__ __align__(16) bf16 g_m2B_lo[NE * NN];
__device__ __align__(16) float g_adjAv[NN * NN];
__device__ __align__(16) float g_adjAe[(size_t)NE * NE];
__device__ __align__(16) float g_HW[NN * DVO];
__device__ __align__(16) float g_HeW[NE * DEO];
__device__ __align__(16) float g_HeWs[NE * DEO];
__device__ __align__(16) float g_de[NE];
__device__ __align__(16) float g_dv[NN];
__device__ u32 g_cmaxu[NE];

// =====================  helpers  =====================
__device__ __forceinline__ u32 smem_u32(const void* p) {
    u32 a;
    asm("{ .reg .u64 t; cvta.to.shared.u64 t, %1; cvt.u32.u64 %0, t; }" : "=r"(a) : "l"(p));
    return a;
}

__device__ __forceinline__ void cp16(u32 saddr, const bf16* gptr) {
    asm volatile("cp.async.cg.shared.global [%0], [%1], 16;"
                 :: "r"(saddr), "l"(__cvta_generic_to_global(gptr)) : "memory");
}

#define LDSM4(r, addr)                                                          \
    asm volatile("ldmatrix.sync.aligned.m8n8.x4.shared.b16 {%0,%1,%2,%3}, [%4];" \
                 : "=r"((r)[0]), "=r"((r)[1]), "=r"((r)[2]), "=r"((r)[3]) : "r"(addr))

#define MMA_BF16(d, a, b)                                                        \
    asm volatile("mma.sync.aligned.m16n8k16.row.col.f32.bf16.bf16.f32 "          \
                 "{%0,%1,%2,%3},{%4,%5,%6,%7},{%8,%9},{%0,%1,%2,%3};"            \
                 : "+f"((d)[0]), "+f"((d)[1]), "+f"((d)[2]), "+f"((d)[3])        \
                 : "r"((a)[0]), "r"((a)[1]), "r"((a)[2]), "r"((a)[3]),           \
                   "r"((b)[0]), "r"((b)[1]))

__device__ __forceinline__ void bsplit(float x, bf16& hi, bf16& lo) {
    hi = __float2bfloat16_rn(x);
    lo = __float2bfloat16_rn(x - __bfloat162float(hi));
}
__device__ __forceinline__ u32 pkb2(bf16 a, bf16 b) {
    __nv_bfloat162 h = __halves2bfloat162(a, b);
    return *(u32*)&h;
}
__device__ __forceinline__ u32 fkey(float f) {
    u32 b = __float_as_uint(f);
    return (b & 0x80000000u) ? ~b : (b | 0x80000000u);
}

// =====================  tiny prologue kernels  =====================
__global__ void k_de(const float* __restrict__ He, const float* __restrict__ pv) {
    int e = blockIdx.x * 256 + threadIdx.x;
    float s = 0.f;
#pragma unroll
    for (int k = 0; k < DEI; k++) s += He[e * DEI + k] * pv[k];
    g_de[e] = s;
}

__global__ void k_hew(const float* __restrict__ He, const float* __restrict__ We) {
    int idx = blockIdx.x * 256 + threadIdx.x;
    int e = idx >> 4, c = idx & 15;
    float s = 0.f;
#pragma unroll
    for (int k = 0; k < DEI; k++) s += He[e * DEI + k] * We[k * DEO + c];
    g_HeW[idx] = s;
}

__global__ void k_hw(const float* __restrict__ Hv, const float* __restrict__ Wv) {
    int idx = blockIdx.x * 256 + threadIdx.x;
    int i = idx >> 6, c = idx & 63;
    float s = 0.f;
#pragma unroll 8
    for (int k = 0; k < KDV; k++) s += Hv[i * KDV + k] * Wv[k * DVO + c];
    g_HW[idx] = s;
}

__global__ void k_cinit() {
    g_cmaxu[blockIdx.x * 256 + threadIdx.x] = 0u;
}

// mult1 prep: B = T (hi/lo), A = T * d_e[col] (hi/lo). [NN][NE] K-major, bf16.
__global__ void k_split1(const float* __restrict__ T) {
    size_t i = (size_t)blockIdx.x * 256 + threadIdx.x;   // float4 index
    float4 t = ((const float4*)T)[i];
    int col = (int)((i * 4) % NE);
    float4 de = *(const float4*)(g_de + col);
    bf16 hx, lx, hy, ly, hz, lz, hw, lw;
    bsplit(t.x, hx, lx); bsplit(t.y, hy, ly); bsplit(t.z, hz, lz); bsplit(t.w, hw, lw);
    ((uint2*)g_m1B_hi)[i] = make_uint2(pkb2(hx, hy), pkb2(hz, hw));
    ((uint2*)g_m1B_lo)[i] = make_uint2(pkb2(lx, ly), pkb2(lz, lw));
    float ax = t.x * de.x, ay = t.y * de.y, az = t.z * de.z, aw = t.w * de.w;
    bsplit(ax, hx, lx); bsplit(ay, hy, ly); bsplit(az, hz, lz); bsplit(aw, hw, lw);
    ((uint2*)g_m1A_hi)[i] = make_uint2(pkb2(hx, hy), pkb2(hz, hw));
    ((uint2*)g_m1A_lo)[i] = make_uint2(pkb2(lx, ly), pkb2(lz, lw));
}

// mult2 prep (transpose): B2[m][k] = T[k][m]; A2[m][k] = T[k][m]*d_v[k]. [NE][NN] bf16.
__global__ void k_split2(const float* __restrict__ T) {
    __shared__ float tile[64][33];
    const int m0 = blockIdx.x * 32, k0 = blockIdx.y * 64;
    const int tx = threadIdx.x, ty = threadIdx.y;     // (32, 8)
#pragma unroll
    for (int j = 0; j < 8; j++) {
        int r = ty + j * 8;
        tile[r][tx] = T[(size_t)(k0 + r) * NE + m0 + tx];
    }
    __syncthreads();
    const int lane = tx, w = ty;
    float2 dv = ((const float2*)(g_dv + k0))[lane];
#pragma unroll
    for (int q = 0; q < 4; q++) {
        const int mloc = w + 8 * q;
        const int m = m0 + mloc;
        float v0 = tile[2 * lane][mloc];
        float v1 = tile[2 * lane + 1][mloc];
        const size_t ob = ((size_t)m * NN + k0) >> 1;   // u32 index
        bf16 h0, l0, h1, l1;
        bsplit(v0, h0, l0); bsplit(v1, h1, l1);
        ((u32*)g_m2B_hi)[ob + lane] = pkb2(h0, h1);
        ((u32*)g_m2B_lo)[ob + lane] = pkb2(l0, l1);
        bsplit(v0 * dv.x, h0, l0); bsplit(v1 * dv.y, h1, l1);
        ((u32*)g_m2A_hi)[ob + lane] = pkb2(h0, h1);
        ((u32*)g_m2A_lo)[ob + lane] = pkb2(l0, l1);
    }
}

// =====================  bf16 3-term tensor-core GEMM, SYMMETRIC (triangular tiles) ========
// Result M is symmetric: compute lower-triangular CTA tiles only.
// Direct block:  C[m0+r][n0+c] = epi(M[r][c]) * adj[m0+r][n0+c]
// Mirror block (off-diag tiles): C[n0+c][m0+r] = M[r][c] * adj[n0+c][m0+r] via smem transpose.
#define KB 32
#define STG_BYTES 32768          // Ahi 8K | Alo 8K | Bhi 8K | Blo 8K
#define NSTAGE 3
#define SMEM_DYN (NSTAGE * STG_BYTES)
#define TP 129                   // transpose pitch (floats)

__device__ __forceinline__ void stage_load(u32 st0, int s,
        const bf16* __restrict__ Ahi, const bf16* __restrict__ Alo,
        const bf16* __restrict__ Bhi, const bf16* __restrict__ Blo,
        int K, int m0, int n0, int k0, int tid) {
    u32 base = st0 + s * STG_BYTES;
#pragma unroll
    for (int i = 0; i < 4; i++) {
        int id = tid + i * 128;                // 0..511
        int r = id >> 2, c = id & 3;           // 128 rows x 4 16B-chunks
        u32 so = (u32)(r * 64 + ((c ^ (r & 3)) << 4));
        size_t gA = (size_t)(m0 + r) * K + k0 + c * 8;
        size_t gB = (size_t)(n0 + r) * K + k0 + c * 8;
        cp16(base + so, Ahi + gA);
        cp16(base + 8192 + so, Alo + gA);
        cp16(base + 16384 + so, Bhi + gB);
        cp16(base + 24576 + so, Blo + gB);
    }
    asm volatile("cp.async.commit_group;" ::: "memory");
}

__global__ __launch_bounds__(128, 2) void k_mult_mma(int which, const float* __restrict__ adj) {
    extern __shared__ char smem[];
    const bf16 *Ahi, *Alo, *Bhi, *Blo;
    float* C;
    int K, ncols;
    if (which == 0) {
        Ahi = g_m1A_hi; Alo = g_m1A_lo; Bhi = g_m1B_hi; Blo = g_m1B_lo;
        C = g_adjAv; K = NE; ncols = NN;
    } else {
        Ahi = g_m2A_hi; Alo = g_m2A_lo; Bhi = g_m2B_hi; Blo = g_m2B_lo;
        C = g_adjAe; K = NN; ncols = NE;
    }
    // triangular tile decode: t -> (bi >= bj)
    const int t = blockIdx.x;
    int bi = (int)((sqrtf(8.0f * (float)t + 1.0f) - 1.0f) * 0.5f);
    while ((bi + 1) * (bi + 2) / 2 <= t) bi++;
    while (bi * (bi + 1) / 2 > t) bi--;
    const int bj = t - bi * (bi + 1) / 2;
    const int m0 = bi * 128, n0 = bj * 128;
    const bool diagtile = (bi == bj);

    const u32 st0 = smem_u32(smem);
    const int tid = threadIdx.x;
    const int lane = tid & 31, wid = tid >> 5;
    const int wm = wid >> 1, wn = wid & 1;          // 2 x 2 warp grid, 64x64 tiles
    const int nk = K / KB;

    float acc[4][8][4];
#pragma unroll
    for (int i = 0; i < 4; i++)
#pragma unroll
        for (int j = 0; j < 8; j++)
#pragma unroll
            for (int q = 0; q < 4; q++) acc[i][j][q] = 0.f;

    stage_load(st0, 0, Ahi, Alo, Bhi, Blo, K, m0, n0, 0, tid);
    stage_load(st0, 1, Ahi, Alo, Bhi, Blo, K, m0, n0, KB, tid);

    const u32 arow = (u32)(wm * 64 + (lane & 15));
    const u32 brow = (u32)(wn * 64 + (lane & 15));
    const u32 asw = arow & 3, bsw = brow & 3;

    for (int kt = 0; kt < nk; kt++) {
        const int s = kt % NSTAGE;
        if (kt + 1 < nk) asm volatile("cp.async.wait_group 1;" ::: "memory");
        else             asm volatile("cp.async.wait_group 0;" ::: "memory");
        __syncthreads();
        if (kt + 2 < nk)
            stage_load(st0, (kt + 2) % NSTAGE, Ahi, Alo, Bhi, Blo, K, m0, n0, (kt + 2) * KB, tid);

        const u32 base = st0 + s * STG_BYTES;
#pragma unroll
        for (int ks = 0; ks < 2; ks++) {
            const u32 cb = (u32)(ks * 2) + (u32)(lane >> 4);
            u32 Bh[8][2], Bl[8][2];
            const u32 boff = base + 16384 + brow * 64 + ((cb ^ bsw) << 4);
#pragma unroll
            for (int nip = 0; nip < 4; nip++) {
                u32 tr[4];
                LDSM4(tr, boff + nip * 1024);
                Bh[2 * nip][0] = tr[0]; Bh[2 * nip][1] = tr[2];
                Bh[2 * nip + 1][0] = tr[1]; Bh[2 * nip + 1][1] = tr[3];
                LDSM4(tr, boff + 8192 + nip * 1024);
                Bl[2 * nip][0] = tr[0]; Bl[2 * nip][1] = tr[2];
                Bl[2 * nip + 1][0] = tr[1]; Bl[2 * nip + 1][1] = tr[3];
            }
            const u32 aoff = base + arow * 64 + ((cb ^ asw) << 4);
#pragma unroll
            for (int mi = 0; mi < 4; mi++) {
                u32 ah[4], al[4];
                LDSM4(ah, aoff + mi * 1024);
                LDSM4(al, aoff + 8192 + mi * 1024);
#pragma unroll
                for (int ni = 0; ni < 8; ni++) {
                    MMA_BF16(acc[mi][ni], ah, Bh[ni]);
                    MMA_BF16(acc[mi][ni], ah, Bl[ni]);
                    MMA_BF16(acc[mi][ni], al, Bh[ni]);
                }
            }
        }
        __syncthreads();
    }

    // ---------- epilogue ----------
    float* stg = (float*)smem;                         // 128 x TP floats (transpose staging)
    u32* scm = (u32*)(smem + 128 * TP * 4);            // 128 u32 colmax (direct block)
    if (which == 1 && tid < 128) scm[tid] = 0u;
    __syncthreads();

    u32 kmax[8][2];
#pragma unroll
    for (int ni = 0; ni < 8; ni++) { kmax[ni][0] = 0u; kmax[ni][1] = 0u; }

#pragma unroll
    for (int mi = 0; mi < 4; mi++) {
#pragma unroll
        for (int h = 0; h < 2; h++) {
            const int row_l = wm * 64 + mi * 16 + (lane >> 2) + h * 8;
            const int row_g = m0 + row_l;
            const size_t rb = (size_t)row_g * ncols;
#pragma unroll
            for (int ni = 0; ni < 8; ni++) {
                const int col_l = wn * 64 + ni * 8 + (lane & 3) * 2;
                const int col_g = n0 + col_l;
                float v0 = acc[mi][ni][h * 2], v1 = acc[mi][ni][h * 2 + 1];
                if (diagtile) {
                    if (row_g == col_g) v0 = 1.0f;
                    if (row_g == col_g + 1) v1 = 1.0f;
                } else {
                    stg[row_l * TP + col_l] = v0;
                    stg[row_l * TP + col_l + 1] = v1;
                }
                const float2 a = *(const float2*)(adj + rb + col_g);
                float w0 = v0 * a.x, w1 = v1 * a.y;
                *(float2*)(C + rb + col_g) = make_float2(w0, w1);
                if (which == 1) {
                    kmax[ni][0] = max(kmax[ni][0], fkey(w0));
                    kmax[ni][1] = max(kmax[ni][1], fkey(w1));
                }
            }
        }
    }
    if (which == 1) {
#pragma unroll
        for (int ni = 0; ni < 8; ni++) {
            const int cl = wn * 64 + ni * 8 + (lane & 3) * 2;
            atomicMax(scm + cl, kmax[ni][0]);
            atomicMax(scm + cl + 1, kmax[ni][1]);
        }
    }
    __syncthreads();
    if (which == 1 && tid < 128) atomicMax(g_cmaxu + n0 + tid, scm[tid]);

    // mirror block: C[n0+c][m0+r] = M[r][c] * adj[n0+c][m0+r]
    if (!diagtile) {
        u32 kloc[4] = {0u, 0u, 0u, 0u};
        for (int cc = 0; cc < 32; cc++) {
            const int c = wid * 32 + cc;
            const size_t orow = (size_t)(n0 + c) * ncols + m0;
#pragma unroll
            for (int ch = 0; ch < 4; ch++) {
                const int r = ch * 32 + lane;
                float v = stg[r * TP + c];
                float w = v * adj[orow + r];
                C[orow + r] = w;
                if (which == 1) kloc[ch] = max(kloc[ch], fkey(w));
            }
        }
        if (which == 1) {
#pragma unroll
            for (int ch = 0; ch < 4; ch++)
                atomicMax(g_cmaxu + m0 + ch * 32 + lane, kloc[ch]);
        }
    }
}

// =====================  Hv_out = adjAv @ HW + b_v  =====================
__global__ __launch_bounds__(256) void k_hv(const float* __restrict__ bv, float* __restrict__ out) {
    __shared__ __align__(16) float As[32 * 32];
    __shared__ __align__(16) float Bs[32 * 64];
    const int tid = threadIdx.x;
    const int tx = tid & 15, ty = tid >> 4;
    const int m0 = blockIdx.x * 32;
    const int arow = tid >> 3, ac4 = (tid & 7) * 4;
    const int brow = tid >> 4, bc4 = (tid & 15) * 4;
    float acc[2][4] = {{0, 0, 0, 0}, {0, 0, 0, 0}};
    for (int k0 = 0; k0 < NN; k0 += 32) {
        float4 fa = *(const float4*)(g_adjAv + (m0 + arow) * NN + k0 + ac4);
        float4 fb0 = *(const float4*)(g_HW + (k0 + brow) * DVO + bc4);
        float4 fb1 = *(const float4*)(g_HW + (k0 + brow + 16) * DVO + bc4);
        __syncthreads();
        As[(ac4 + 0) * 32 + arow] = fa.x; As[(ac4 + 1) * 32 + arow] = fa.y;
        As[(ac4 + 2) * 32 + arow] = fa.z; As[(ac4 + 3) * 32 + arow] = fa.w;
        *(float4*)(Bs + brow * 64 + bc4) = fb0;
        *(float4*)(Bs + (brow + 16) * 64 + bc4) = fb1;
        __syncthreads();
#pragma unroll
        for (int kk = 0; kk < 32; kk++) {
            float a0 = As[kk * 32 + ty * 2];
            float a1 = As[kk * 32 + ty * 2 + 1];
            float4 b = *(const float4*)(Bs + kk * 64 + tx * 4);
            acc[0][0] += a0 * b.x; acc[0][1] += a0 * b.y; acc[0][2] += a0 * b.z; acc[0][3] += a0 * b.w;
            acc[1][0] += a1 * b.x; acc[1][1] += a1 * b.y; acc[1][2] += a1 * b.z; acc[1][3] += a1 * b.w;
        }
    }
    float4 bb = *(const float4*)(bv + tx * 4);
#pragma unroll
    for (int r = 0; r < 2; r++) {
        int row = m0 + ty * 2 + r;
        *(float4*)(out + row * DVO + tx * 4) =
            make_float4(acc[r][0] + bb.x, acc[r][1] + bb.y, acc[r][2] + bb.z, acc[r][3] + bb.w);
    }
}

__global__ void k_dv(const float* __restrict__ Hv, const float* __restrict__ pe) {
    int w = (blockIdx.x * blockDim.x + threadIdx.x) >> 5;
    int lane = threadIdx.x & 31;
    float s = Hv[w * DVO + lane] * pe[lane] + Hv[w * DVO + 32 + lane] * pe[32 + lane];
#pragma unroll
    for (int o = 16; o > 0; o >>= 1) s += __shfl_down_sync(0xffffffffu, s, o);
    if (lane == 0) g_dv[w] = s;
}

// finalize colmax from keys, fold 1/(max+1e-10) into HeW -> HeWs
__global__ void k_cmax2() {
    int col = blockIdx.x * 256 + threadIdx.x;
    u32 k = g_cmaxu[col];
    u32 b = (k & 0x80000000u) ? (k ^ 0x80000000u) : ~k;
    float m = __uint_as_float(b);
    float inv = 1.0f / (m + 1e-10f);
#pragma unroll
    for (int c = 0; c < DEO; c++) g_HeWs[col * DEO + c] = g_HeW[col * DEO + c] * inv;
}

__global__ __launch_bounds__(256) void k_he(const float* __restrict__ be, float* __restrict__ out) {
    __shared__ __align__(16) float As[64 * 64];
    __shared__ __align__(16) float Bs[64 * 16];
    const int tid = threadIdx.x;
    const int c = tid & 15, tr = tid >> 4;
    const int m0 = blockIdx.x * 64;
    const int lc4 = (tid & 15) * 4;
    float acc[4] = {0, 0, 0, 0};
    for (int k0 = 0; k0 < NE; k0 += 64) {
        float4 ra[4]; float rb[4];
#pragma unroll
        for (int q = 0; q < 4; q++) {
            int row = tr + q * 16;
            ra[q] = *(const float4*)(g_adjAe + (size_t)(m0 + row) * NE + k0 + lc4);
            rb[q] = g_HeWs[(k0 + row) * DEO + c];
        }
        __syncthreads();
#pragma unroll
        for (int q = 0; q < 4; q++) {
            int row = tr + q * 16;
            *(float4*)(As + row * 64 + lc4) = ra[q];
            Bs[row * 16 + c] = rb[q];
        }
        __syncthreads();
#pragma unroll 8
        for (int kk = 0; kk < 64; kk++) {
            float b = Bs[kk * 16 + c];
            acc[0] += As[(0 * 16 + tr) * 64 + kk] * b;
            acc[1] += As[(1 * 16 + tr) * 64 + kk] * b;
            acc[2] += As[(2 * 16 + tr) * 64 + kk] * b;
            acc[3] += As[(3 * 16 + tr) * 64 + kk] * b;
        }
    }
    float bc = be[c];
#pragma unroll
    for (int q = 0; q < 4; q++)
        out[(m0 + q * 16 + tr) * DEO + c] = acc[q] + bc;
}

// =====================  launch  =====================
extern "C" void kernel_launch(void* const* d_in, const int* in_sizes, int n_in,
                              void* d_out, int out_size) {
    const float* H_v  = (const float*)d_in[0];
    const float* H_e  = (const float*)d_in[1];
    const float* adjv = (const float*)d_in[2];
    const float* adje = (const float*)d_in[3];
    const float* T    = (const float*)d_in[4];
    const float* W_v  = (const float*)d_in[5];
    const float* b_v  = (const float*)d_in[6];
    const float* p_v  = (const float*)d_in[7];
    const float* W_e  = (const float*)d_in[8];
    const float* b_e  = (const float*)d_in[9];
    const float* p_e  = (const float*)d_in[10];
    float* out = (float*)d_out;
    (void)in_sizes; (void)n_in; (void)out_size;

    cudaFuncSetAttribute(k_mult_mma, cudaFuncAttributeMaxDynamicSharedMemorySize, SMEM_DYN);

    k_de<<<24, 256>>>(H_e, p_v);
    k_hew<<<384, 256>>>(H_e, W_e);
    k_hw<<<512, 256>>>(H_v, W_v);
    k_cinit<<<24, 256>>>();
    k_split1<<<12288, 256>>>(T);
    k_mult_mma<<<136, 128, SMEM_DYN>>>(0, adjv);    // adjAv, triangular (16x16 -> 136 tiles)
    k_hv<<<64, 256>>>(b_v, out);
    k_dv<<<256, 256>>>(out, p_e);
    k_split2<<<dim3(192, 32), dim3(32, 8)>>>(T);
    k_mult_mma<<<1176, 128, SMEM_DYN>>>(1, adje);   // adjAe, triangular (48x48 -> 1176 tiles)
    k_cmax2<<<24, 256>>>();
    k_he<<<96, 256>>>(b_e, out + NN * DVO);
}

// round 9
// speedup vs baseline: 1.7361x; 1.0724x over previous
#include <cuda_runtime.h>
#include <cuda_fp16.h>
#include <cstdint>

typedef unsigned int u32;
typedef unsigned long long u64;

#define NN 2048
#define NE 6144
#define KDV 128
#define DVO 64
#define DEI 16
#define DEO 16

#define DV_SCALE (1.0f / 256.0f)
#define DV_UNSCALE 256.0f

// =====================  scratch  =====================
__device__ __align__(16) __half g_m1A_hi[NN * NE];
__device__ __align__(16) __half g_m1A_lo[NN * NE];
__device__ __align__(16) __half g_m1B_hi[NN * NE];
__device__ __align__(16) __half g_m1B_lo[NN * NE];
__device__ __align__(16) __half g_m2A_hi[NE * NN];      // scaled by 2^-8
__device__ __align__(16) __half g_m2B_hi[NE * NN];
__device__ __align__(16) __half g_m2B_lo[NE * NN];
__device__ __align__(16) float g_adjAv[NN * NN];
__device__ __align__(16) float g_adjAe[(size_t)NE * NE];
__device__ __align__(16) float g_HW[NN * DVO];
__device__ __align__(16) float g_HeW[NE * DEO];
__device__ __align__(16) float g_HeWs[NE * DEO];
__device__ __align__(16) float g_de[NE];
__device__ __align__(16) float g_dv[NN];
__device__ u32 g_cmaxu[NE];

// =====================  helpers  =====================
__device__ __forceinline__ u32 smem_u32(const void* p) {
    u32 a;
    asm("{ .reg .u64 t; cvta.to.shared.u64 t, %1; cvt.u32.u64 %0, t; }" : "=r"(a) : "l"(p));
    return a;
}

__device__ __forceinline__ void cp16(u32 saddr, const __half* gptr) {
    asm volatile("cp.async.cg.shared.global [%0], [%1], 16;"
                 :: "r"(saddr), "l"(__cvta_generic_to_global(gptr)) : "memory");
}

#define LDSM4(r, addr)                                                          \
    asm volatile("ldmatrix.sync.aligned.m8n8.x4.shared.b16 {%0,%1,%2,%3}, [%4];" \
                 : "=r"((r)[0]), "=r"((r)[1]), "=r"((r)[2]), "=r"((r)[3]) : "r"(addr))

#define MMA_F16(d, a, b)                                                         \
    asm volatile("mma.sync.aligned.m16n8k16.row.col.f32.f16.f16.f32 "            \
                 "{%0,%1,%2,%3},{%4,%5,%6,%7},{%8,%9},{%0,%1,%2,%3};"            \
                 : "+f"((d)[0]), "+f"((d)[1]), "+f"((d)[2]), "+f"((d)[3])        \
                 : "r"((a)[0]), "r"((a)[1]), "r"((a)[2]), "r"((a)[3]),           \
                   "r"((b)[0]), "r"((b)[1]))

__device__ __forceinline__ void hsplit(float x, __half& hi, __half& lo) {
    hi = __float2half_rn(x);
    lo = __float2half_rn(x - __half2float(hi));
}
__device__ __forceinline__ u32 pkh2(__half a, __half b) {
    __half2 h = __halves2half2(a, b);
    return *(u32*)&h;
}
__device__ __forceinline__ u32 fkey(float f) {
    u32 b = __float_as_uint(f);
    return (b & 0x80000000u) ? ~b : (b | 0x80000000u);
}

// =====================  tiny prologue kernels  =====================
__global__ void k_de(const float* __restrict__ He, const float* __restrict__ pv) {
    int e = blockIdx.x * 256 + threadIdx.x;
    float s = 0.f;
#pragma unroll
    for (int k = 0; k < DEI; k++) s += He[e * DEI + k] * pv[k];
    g_de[e] = s;
}

__global__ void k_hew(const float* __restrict__ He, const float* __restrict__ We) {
    int idx = blockIdx.x * 256 + threadIdx.x;
    int e = idx >> 4, c = idx & 15;
    float s = 0.f;
#pragma unroll
    for (int k = 0; k < DEI; k++) s += He[e * DEI + k] * We[k * DEO + c];
    g_HeW[idx] = s;
}

__global__ void k_hw(const float* __restrict__ Hv, const float* __restrict__ Wv) {
    int idx = blockIdx.x * 256 + threadIdx.x;
    int i = idx >> 6, c = idx & 63;
    float s = 0.f;
#pragma unroll 8
    for (int k = 0; k < KDV; k++) s += Hv[i * KDV + k] * Wv[k * DVO + c];
    g_HW[idx] = s;
}

__global__ void k_cinit() {
    g_cmaxu[blockIdx.x * 256 + threadIdx.x] = 0u;
}

// mult1 prep: B = T (hi/lo), A = T * d_e[col] (hi/lo). [NN][NE] K-major, fp16.
__global__ void k_split1(const float* __restrict__ T) {
    size_t i = (size_t)blockIdx.x * 256 + threadIdx.x;   // float4 index
    float4 t = ((const float4*)T)[i];
    int col = (int)((i * 4) % NE);
    float4 de = *(const float4*)(g_de + col);
    __half hx, lx, hy, ly, hz, lz, hw, lw;
    hsplit(t.x, hx, lx); hsplit(t.y, hy, ly); hsplit(t.z, hz, lz); hsplit(t.w, hw, lw);
    ((uint2*)g_m1B_hi)[i] = make_uint2(pkh2(hx, hy), pkh2(hz, hw));
    ((uint2*)g_m1B_lo)[i] = make_uint2(pkh2(lx, ly), pkh2(lz, lw));
    float ax = t.x * de.x, ay = t.y * de.y, az = t.z * de.z, aw = t.w * de.w;
    hsplit(ax, hx, lx); hsplit(ay, hy, ly); hsplit(az, hz, lz); hsplit(aw, hw, lw);
    ((uint2*)g_m1A_hi)[i] = make_uint2(pkh2(hx, hy), pkh2(hz, hw));
    ((uint2*)g_m1A_lo)[i] = make_uint2(pkh2(lx, ly), pkh2(lz, lw));
}

// mult2 prep (transpose): B2[m][k] = T[k][m] (hi/lo); A2[m][k] = T[k][m]*d_v[k]*2^-8 (hi only).
__global__ void k_split2(const float* __restrict__ T) {
    __shared__ float tile[64][33];
    const int m0 = blockIdx.x * 32, k0 = blockIdx.y * 64;
    const int tx = threadIdx.x, ty = threadIdx.y;     // (32, 8)
#pragma unroll
    for (int j = 0; j < 8; j++) {
        int r = ty + j * 8;
        tile[r][tx] = T[(size_t)(k0 + r) * NE + m0 + tx];
    }
    __syncthreads();
    const int lane = tx, w = ty;
    float2 dv = ((const float2*)(g_dv + k0))[lane];
    dv.x *= DV_SCALE; dv.y *= DV_SCALE;
#pragma unroll
    for (int q = 0; q < 4; q++) {
        const int mloc = w + 8 * q;
        const int m = m0 + mloc;
        float v0 = tile[2 * lane][mloc];
        float v1 = tile[2 * lane + 1][mloc];
        const size_t ob = ((size_t)m * NN + k0) >> 1;   // u32 index
        __half h0, l0, h1, l1;
        hsplit(v0, h0, l0); hsplit(v1, h1, l1);
        ((u32*)g_m2B_hi)[ob + lane] = pkh2(h0, h1);
        ((u32*)g_m2B_lo)[ob + lane] = pkh2(l0, l1);
        ((u32*)g_m2A_hi)[ob + lane] =
            pkh2(__float2half_rn(v0 * dv.x), __float2half_rn(v1 * dv.y));
    }
}

// =====================  fp16 tensor-core GEMM, SYMMETRIC (triangular tiles)  ========
// which==0: 3-term (Ahi*Bhi + Ahi*Blo + Alo*Bhi), oscale=1
// which==1: 2-term (Ahi*Bhi + Ahi*Blo),           oscale=256 (undo dv scaling)
#define KB 32
#define STG_BYTES 32768          // Ahi 8K | Alo 8K | Bhi 8K | Blo 8K
#define NSTAGE 3
#define SMEM_DYN (NSTAGE * STG_BYTES)
#define TP 129                   // transpose pitch (floats)

__device__ __forceinline__ void stage_load(u32 st0, int s,
        const __half* __restrict__ Ahi, const __half* __restrict__ Alo,
        const __half* __restrict__ Bhi, const __half* __restrict__ Blo,
        int K, int m0, int n0, int k0, int tid, bool loadAlo) {
    u32 base = st0 + s * STG_BYTES;
#pragma unroll
    for (int i = 0; i < 4; i++) {
        int id = tid + i * 128;                // 0..511
        int r = id >> 2, c = id & 3;           // 128 rows x 4 16B-chunks
        u32 so = (u32)(r * 64 + ((c ^ (r & 3)) << 4));
        size_t gA = (size_t)(m0 + r) * K + k0 + c * 8;
        size_t gB = (size_t)(n0 + r) * K + k0 + c * 8;
        cp16(base + so, Ahi + gA);
        if (loadAlo) cp16(base + 8192 + so, Alo + gA);
        cp16(base + 16384 + so, Bhi + gB);
        cp16(base + 24576 + so, Blo + gB);
    }
    asm volatile("cp.async.commit_group;" ::: "memory");
}

__global__ __launch_bounds__(128, 2) void k_mult_mma(int which, const float* __restrict__ adj) {
    extern __shared__ char smem[];
    const __half *Ahi, *Alo, *Bhi, *Blo;
    float* C;
    int K, ncols;
    float oscale;
    if (which == 0) {
        Ahi = g_m1A_hi; Alo = g_m1A_lo; Bhi = g_m1B_hi; Blo = g_m1B_lo;
        C = g_adjAv; K = NE; ncols = NN; oscale = 1.0f;
    } else {
        Ahi = g_m2A_hi; Alo = g_m2A_hi; Bhi = g_m2B_hi; Blo = g_m2B_lo;
        C = g_adjAe; K = NN; ncols = NE; oscale = DV_UNSCALE;
    }
    const bool threeterm = (which == 0);
    // triangular tile decode: t -> (bi >= bj)
    const int t = blockIdx.x;
    int bi = (int)((sqrtf(8.0f * (float)t + 1.0f) - 1.0f) * 0.5f);
    while ((bi + 1) * (bi + 2) / 2 <= t) bi++;
    while (bi * (bi + 1) / 2 > t) bi--;
    const int bj = t - bi * (bi + 1) / 2;
    const int m0 = bi * 128, n0 = bj * 128;
    const bool diagtile = (bi == bj);

    const u32 st0 = smem_u32(smem);
    const int tid = threadIdx.x;
    const int lane = tid & 31, wid = tid >> 5;
    const int wm = wid >> 1, wn = wid & 1;          // 2 x 2 warp grid, 64x64 tiles
    const int nk = K / KB;

    float acc[4][8][4];
#pragma unroll
    for (int i = 0; i < 4; i++)
#pragma unroll
        for (int j = 0; j < 8; j++)
#pragma unroll
            for (int q = 0; q < 4; q++) acc[i][j][q] = 0.f;

    stage_load(st0, 0, Ahi, Alo, Bhi, Blo, K, m0, n0, 0, tid, threeterm);
    stage_load(st0, 1, Ahi, Alo, Bhi, Blo, K, m0, n0, KB, tid, threeterm);

    const u32 arow = (u32)(wm * 64 + (lane & 15));
    const u32 brow = (u32)(wn * 64 + (lane & 15));
    const u32 asw = arow & 3, bsw = brow & 3;

    for (int kt = 0; kt < nk; kt++) {
        const int s = kt % NSTAGE;
        if (kt + 1 < nk) asm volatile("cp.async.wait_group 1;" ::: "memory");
        else             asm volatile("cp.async.wait_group 0;" ::: "memory");
        __syncthreads();
        if (kt + 2 < nk)
            stage_load(st0, (kt + 2) % NSTAGE, Ahi, Alo, Bhi, Blo, K, m0, n0,
                       (kt + 2) * KB, tid, threeterm);

        const u32 base = st0 + s * STG_BYTES;
#pragma unroll
        for (int ks = 0; ks < 2; ks++) {
            const u32 cb = (u32)(ks * 2) + (u32)(lane >> 4);
            u32 Bh[8][2], Bl[8][2];
            const u32 boff = base + 16384 + brow * 64 + ((cb ^ bsw) << 4);
#pragma unroll
            for (int nip = 0; nip < 4; nip++) {
                u32 tr[4];
                LDSM4(tr, boff + nip * 1024);
                Bh[2 * nip][0] = tr[0]; Bh[2 * nip][1] = tr[2];
                Bh[2 * nip + 1][0] = tr[1]; Bh[2 * nip + 1][1] = tr[3];
                LDSM4(tr, boff + 8192 + nip * 1024);
                Bl[2 * nip][0] = tr[0]; Bl[2 * nip][1] = tr[2];
                Bl[2 * nip + 1][0] = tr[1]; Bl[2 * nip + 1][1] = tr[3];
            }
            const u32 aoff = base + arow * 64 + ((cb ^ asw) << 4);
            if (threeterm) {
#pragma unroll
                for (int mi = 0; mi < 4; mi++) {
                    u32 ah[4], al[4];
                    LDSM4(ah, aoff + mi * 1024);
                    LDSM4(al, aoff + 8192 + mi * 1024);
#pragma unroll
                    for (int ni = 0; ni < 8; ni++) {
                        MMA_F16(acc[mi][ni], ah, Bh[ni]);
                        MMA_F16(acc[mi][ni], ah, Bl[ni]);
                        MMA_F16(acc[mi][ni], al, Bh[ni]);
                    }
                }
            } else {
#pragma unroll
                for (int mi = 0; mi < 4; mi++) {
                    u32 ah[4];
                    LDSM4(ah, aoff + mi * 1024);
#pragma unroll
                    for (int ni = 0; ni < 8; ni++) {
                        MMA_F16(acc[mi][ni], ah, Bh[ni]);
                        MMA_F16(acc[mi][ni], ah, Bl[ni]);
                    }
                }
            }
        }
        __syncthreads();
    }

    // ---------- epilogue ----------
    float* stg = (float*)smem;                         // 128 x TP floats (transpose staging)
    u32* scm = (u32*)(smem + 128 * TP * 4);            // 128 u32 colmax (direct block)
    if (which == 1 && tid < 128) scm[tid] = 0u;
    __syncthreads();

    u32 kmax[8][2];
#pragma unroll
    for (int ni = 0; ni < 8; ni++) { kmax[ni][0] = 0u; kmax[ni][1] = 0u; }

#pragma unroll
    for (int mi = 0; mi < 4; mi++) {
#pragma unroll
        for (int h = 0; h < 2; h++) {
            const int row_l = wm * 64 + mi * 16 + (lane >> 2) + h * 8;
            const int row_g = m0 + row_l;
            const size_t rb = (size_t)row_g * ncols;
#pragma unroll
            for (int ni = 0; ni < 8; ni++) {
                const int col_l = wn * 64 + ni * 8 + (lane & 3) * 2;
                const int col_g = n0 + col_l;
                float v0 = acc[mi][ni][h * 2] * oscale;
                float v1 = acc[mi][ni][h * 2 + 1] * oscale;
                if (diagtile) {
                    if (row_g == col_g) v0 = 1.0f;
                    if (row_g == col_g + 1) v1 = 1.0f;
                } else {
                    stg[row_l * TP + col_l] = v0;
                    stg[row_l * TP + col_l + 1] = v1;
                }
                const float2 a = *(const float2*)(adj + rb + col_g);
                float w0 = v0 * a.x, w1 = v1 * a.y;
                *(float2*)(C + rb + col_g) = make_float2(w0, w1);
                if (which == 1) {
                    kmax[ni][0] = max(kmax[ni][0], fkey(w0));
                    kmax[ni][1] = max(kmax[ni][1], fkey(w1));
                }
            }
        }
    }
    if (which == 1) {
#pragma unroll
        for (int ni = 0; ni < 8; ni++) {
            const int cl = wn * 64 + ni * 8 + (lane & 3) * 2;
            atomicMax(scm + cl, kmax[ni][0]);
            atomicMax(scm + cl + 1, kmax[ni][1]);
        }
    }
    __syncthreads();
    if (which == 1 && tid < 128) atomicMax(g_cmaxu + n0 + tid, scm[tid]);

    // mirror block: C[n0+c][m0+r] = M[r][c] * adj[n0+c][m0+r]
    if (!diagtile) {
        u32 kloc[4] = {0u, 0u, 0u, 0u};
        for (int cc = 0; cc < 32; cc++) {
            const int c = wid * 32 + cc;
            const size_t orow = (size_t)(n0 + c) * ncols + m0;
#pragma unroll
            for (int ch = 0; ch < 4; ch++) {
                const int r = ch * 32 + lane;
                float v = stg[r * TP + c];
                float w = v * adj[orow + r];
                C[orow + r] = w;
                if (which == 1) kloc[ch] = max(kloc[ch], fkey(w));
            }
        }
        if (which == 1) {
#pragma unroll
            for (int ch = 0; ch < 4; ch++)
                atomicMax(g_cmaxu + m0 + ch * 32 + lane, kloc[ch]);
        }
    }
}

// =====================  Hv_out = adjAv @ HW + b_v  =====================
__global__ __launch_bounds__(256) void k_hv(const float* __restrict__ bv, float* __restrict__ out) {
    __shared__ __align__(16) float As[32 * 32];
    __shared__ __align__(16) float Bs[32 * 64];
    const int tid = threadIdx.x;
    const int tx = tid & 15, ty = tid >> 4;
    const int m0 = blockIdx.x * 32;
    const int arow = tid >> 3, ac4 = (tid & 7) * 4;
    const int brow = tid >> 4, bc4 = (tid & 15) * 4;
    float acc[2][4] = {{0, 0, 0, 0}, {0, 0, 0, 0}};
    for (int k0 = 0; k0 < NN; k0 += 32) {
        float4 fa = *(const float4*)(g_adjAv + (m0 + arow) * NN + k0 + ac4);
        float4 fb0 = *(const float4*)(g_HW + (k0 + brow) * DVO + bc4);
        float4 fb1 = *(const float4*)(g_HW + (k0 + brow + 16) * DVO + bc4);
        __syncthreads();
        As[(ac4 + 0) * 32 + arow] = fa.x; As[(ac4 + 1) * 32 + arow] = fa.y;
        As[(ac4 + 2) * 32 + arow] = fa.z; As[(ac4 + 3) * 32 + arow] = fa.w;
        *(float4*)(Bs + brow * 64 + bc4) = fb0;
        *(float4*)(Bs + (brow + 16) * 64 + bc4) = fb1;
        __syncthreads();
#pragma unroll
        for (int kk = 0; kk < 32; kk++) {
            float a0 = As[kk * 32 + ty * 2];
            float a1 = As[kk * 32 + ty * 2 + 1];
            float4 b = *(const float4*)(Bs + kk * 64 + tx * 4);
            acc[0][0] += a0 * b.x; acc[0][1] += a0 * b.y; acc[0][2] += a0 * b.z; acc[0][3] += a0 * b.w;
            acc[1][0] += a1 * b.x; acc[1][1] += a1 * b.y; acc[1][2] += a1 * b.z; acc[1][3] += a1 * b.w;
        }
    }
    float4 bb = *(const float4*)(bv + tx * 4);
#pragma unroll
    for (int r = 0; r < 2; r++) {
        int row = m0 + ty * 2 + r;
        *(float4*)(out + row * DVO + tx * 4) =
            make_float4(acc[r][0] + bb.x, acc[r][1] + bb.y, acc[r][2] + bb.z, acc[r][3] + bb.w);
    }
}

__global__ void k_dv(const float* __restrict__ Hv, const float* __restrict__ pe) {
    int w = (blockIdx.x * blockDim.x + threadIdx.x) >> 5;
    int lane = threadIdx.x & 31;
    float s = Hv[w * DVO + lane] * pe[lane] + Hv[w * DVO + 32 + lane] * pe[32 + lane];
#pragma unroll
    for (int o = 16; o > 0; o >>= 1) s += __shfl_down_sync(0xffffffffu, s, o);
    if (lane == 0) g_dv[w] = s;
}

// finalize colmax from keys, fold 1/(max+1e-10) into HeW -> HeWs
__global__ void k_cmax2() {
    int col = blockIdx.x * 256 + threadIdx.x;
    u32 k = g_cmaxu[col];
    u32 b = (k & 0x80000000u) ? (k ^ 0x80000000u) : ~k;
    float m = __uint_as_float(b);
    float inv = 1.0f / (m + 1e-10f);
#pragma unroll
    for (int c = 0; c < DEO; c++) g_HeWs[col * DEO + c] = g_HeW[col * DEO + c] * inv;
}

__global__ __launch_bounds__(256) void k_he(const float* __restrict__ be, float* __restrict__ out) {
    __shared__ __align__(16) float As[64 * 64];
    __shared__ __align__(16) float Bs[64 * 16];
    const int tid = threadIdx.x;
    const int c = tid & 15, tr = tid >> 4;
    const int m0 = blockIdx.x * 64;
    const int lc4 = (tid & 15) * 4;
    float acc[4] = {0, 0, 0, 0};
    for (int k0 = 0; k0 < NE; k0 += 64) {
        float4 ra[4]; float rb[4];
#pragma unroll
        for (int q = 0; q < 4; q++) {
            int row = tr + q * 16;
            ra[q] = *(const float4*)(g_adjAe + (size_t)(m0 + row) * NE + k0 + lc4);
            rb[q] = g_HeWs[(k0 + row) * DEO + c];
        }
        __syncthreads();
#pragma unroll
        for (int q = 0; q < 4; q++) {
            int row = tr + q * 16;
            *(float4*)(As + row * 64 + lc4) = ra[q];
            Bs[row * 16 + c] = rb[q];
        }
        __syncthreads();
#pragma unroll 8
        for (int kk = 0; kk < 64; kk++) {
            float b = Bs[kk * 16 + c];
            acc[0] += As[(0 * 16 + tr) * 64 + kk] * b;
            acc[1] += As[(1 * 16 + tr) * 64 + kk] * b;
            acc[2] += As[(2 * 16 + tr) * 64 + kk] * b;
            acc[3] += As[(3 * 16 + tr) * 64 + kk] * b;
        }
    }
    float bc = be[c];
#pragma unroll
    for (int q = 0; q < 4; q++)
        out[(m0 + q * 16 + tr) * DEO + c] = acc[q] + bc;
}

// =====================  launch  =====================
extern "C" void kernel_launch(void* const* d_in, const int* in_sizes, int n_in,
                              void* d_out, int out_size) {
    const float* H_v  = (const float*)d_in[0];
    const float* H_e  = (const float*)d_in[1];
    const float* adjv = (const float*)d_in[2];
    const float* adje = (const float*)d_in[3];
    const float* T    = (const float*)d_in[4];
    const float* W_v  = (const float*)d_in[5];
    const float* b_v  = (const float*)d_in[6];
    const float* p_v  = (const float*)d_in[7];
    const float* W_e  = (const float*)d_in[8];
    const float* b_e  = (const float*)d_in[9];
    const float* p_e  = (const float*)d_in[10];
    float* out = (float*)d_out;
    (void)in_sizes; (void)n_in; (void)out_size;

    cudaFuncSetAttribute(k_mult_mma, cudaFuncAttributeMaxDynamicSharedMemorySize, SMEM_DYN);

    k_de<<<24, 256>>>(H_e, p_v);
    k_hew<<<384, 256>>>(H_e, W_e);
    k_hw<<<512, 256>>>(H_v, W_v);
    k_cinit<<<24, 256>>>();
    k_split1<<<12288, 256>>>(T);
    k_mult_mma<<<136, 128, SMEM_DYN>>>(0, adjv);    // adjAv, fp16 3-term, triangular
    k_hv<<<64, 256>>>(b_v, out);
    k_dv<<<256, 256>>>(out, p_e);
    k_split2<<<dim3(192, 32), dim3(32, 8)>>>(T);
    k_mult_mma<<<1176, 128, SMEM_DYN>>>(1, adje);   // adjAe, fp16 2-term, triangular
    k_cmax2<<<24, 256>>>();
    k_he<<<96, 256>>>(b_e, out + NN * DVO);
}

// round 10
// speedup vs baseline: 2.1791x; 1.2552x over previous
#include <cuda_runtime.h>
#include <cuda_fp16.h>
#include <cstdint>

typedef unsigned int u32;
typedef unsigned long long u64;

#define NN 2048
#define NE 6144
#define KDV 128
#define DVO 64
#define DEI 16
#define DEO 16

#define DV_SCALE (1.0f / 256.0f)
#define DV_UNSCALE 256.0f

// =====================  scratch  =====================
__device__ __align__(16) __half g_m1A_hi[NN * NE];      // fp16(T * d_e[col])
__device__ __align__(16) __half g_m1B_hi[NN * NE];
__device__ __align__(16) __half g_m1B_lo[NN * NE];
__device__ __align__(16) __half g_m2A_hi[NE * NN];      // fp16(T^T * d_v * 2^-8)
__device__ __align__(16) __half g_m2B_hi[NE * NN];
__device__ __align__(16) __half g_m2B_lo[NE * NN];
__device__ __align__(16) float g_adjAv[NN * NN];
__device__ __align__(16) float g_adjAe[(size_t)NE * NE];
__device__ __align__(16) float g_HW[NN * DVO];
__device__ __align__(16) float g_HeW[NE * DEO];
__device__ __align__(16) float g_HeWs[NE * DEO];
__device__ __align__(16) float g_de[NE];
__device__ __align__(16) float g_dv[NN];
__device__ u32 g_cmaxu[NE];

// =====================  helpers  =====================
__device__ __forceinline__ u32 smem_u32(const void* p) {
    u32 a;
    asm("{ .reg .u64 t; cvta.to.shared.u64 t, %1; cvt.u32.u64 %0, t; }" : "=r"(a) : "l"(p));
    return a;
}

__device__ __forceinline__ void cp16(u32 saddr, const __half* gptr) {
    asm volatile("cp.async.cg.shared.global [%0], [%1], 16;"
                 :: "r"(saddr), "l"(__cvta_generic_to_global(gptr)) : "memory");
}

#define LDSM4(r, addr)                                                          \
    asm volatile("ldmatrix.sync.aligned.m8n8.x4.shared.b16 {%0,%1,%2,%3}, [%4];" \
                 : "=r"((r)[0]), "=r"((r)[1]), "=r"((r)[2]), "=r"((r)[3]) : "r"(addr))

#define MMA_F16(d, a, b)                                                         \
    asm volatile("mma.sync.aligned.m16n8k16.row.col.f32.f16.f16.f32 "            \
                 "{%0,%1,%2,%3},{%4,%5,%6,%7},{%8,%9},{%0,%1,%2,%3};"            \
                 : "+f"((d)[0]), "+f"((d)[1]), "+f"((d)[2]), "+f"((d)[3])        \
                 : "r"((a)[0]), "r"((a)[1]), "r"((a)[2]), "r"((a)[3]),           \
                   "r"((b)[0]), "r"((b)[1]))

__device__ __forceinline__ void hsplit(float x, __half& hi, __half& lo) {
    hi = __float2half_rn(x);
    lo = __float2half_rn(x - __half2float(hi));
}
__device__ __forceinline__ u32 pkh2(__half a, __half b) {
    __half2 h = __halves2half2(a, b);
    return *(u32*)&h;
}
__device__ __forceinline__ u32 fkey(float f) {
    u32 b = __float_as_uint(f);
    return (b & 0x80000000u) ? ~b : (b | 0x80000000u);
}

// =====================  tiny prologue kernels  =====================
__global__ void k_de(const float* __restrict__ He, const float* __restrict__ pv) {
    int e = blockIdx.x * 256 + threadIdx.x;
    float s = 0.f;
#pragma unroll
    for (int k = 0; k < DEI; k++) s += He[e * DEI + k] * pv[k];
    g_de[e] = s;
}

__global__ void k_hew(const float* __restrict__ He, const float* __restrict__ We) {
    int idx = blockIdx.x * 256 + threadIdx.x;
    int e = idx >> 4, c = idx & 15;
    float s = 0.f;
#pragma unroll
    for (int k = 0; k < DEI; k++) s += He[e * DEI + k] * We[k * DEO + c];
    g_HeW[idx] = s;
}

__global__ void k_hw(const float* __restrict__ Hv, const float* __restrict__ Wv) {
    int idx = blockIdx.x * 256 + threadIdx.x;
    int i = idx >> 6, c = idx & 63;
    float s = 0.f;
#pragma unroll 8
    for (int k = 0; k < KDV; k++) s += Hv[i * KDV + k] * Wv[k * DVO + c];
    g_HW[idx] = s;
}

__global__ void k_cinit() {
    g_cmaxu[blockIdx.x * 256 + threadIdx.x] = 0u;
}

// mult1 prep: B = T (hi/lo), A = fp16(T * d_e[col]). [NN][NE] K-major.
__global__ void k_split1(const float* __restrict__ T) {
    size_t i = (size_t)blockIdx.x * 256 + threadIdx.x;   // float4 index
    float4 t = ((const float4*)T)[i];
    int col = (int)((i * 4) % NE);
    float4 de = *(const float4*)(g_de + col);
    __half hx, lx, hy, ly, hz, lz, hw, lw;
    hsplit(t.x, hx, lx); hsplit(t.y, hy, ly); hsplit(t.z, hz, lz); hsplit(t.w, hw, lw);
    ((uint2*)g_m1B_hi)[i] = make_uint2(pkh2(hx, hy), pkh2(hz, hw));
    ((uint2*)g_m1B_lo)[i] = make_uint2(pkh2(lx, ly), pkh2(lz, lw));
    ((uint2*)g_m1A_hi)[i] = make_uint2(
        pkh2(__float2half_rn(t.x * de.x), __float2half_rn(t.y * de.y)),
        pkh2(__float2half_rn(t.z * de.z), __float2half_rn(t.w * de.w)));
}

// mult2 prep (transpose): B2[m][k] = T[k][m] (hi/lo); A2[m][k] = fp16(T[k][m]*d_v[k]*2^-8).
__global__ void k_split2(const float* __restrict__ T) {
    __shared__ float tile[64][33];
    const int m0 = blockIdx.x * 32, k0 = blockIdx.y * 64;
    const int tx = threadIdx.x, ty = threadIdx.y;     // (32, 8)
#pragma unroll
    for (int j = 0; j < 8; j++) {
        int r = ty + j * 8;
        tile[r][tx] = T[(size_t)(k0 + r) * NE + m0 + tx];
    }
    __syncthreads();
    const int lane = tx, w = ty;
    float2 dv = ((const float2*)(g_dv + k0))[lane];
    dv.x *= DV_SCALE; dv.y *= DV_SCALE;
#pragma unroll
    for (int q = 0; q < 4; q++) {
        const int mloc = w + 8 * q;
        const int m = m0 + mloc;
        float v0 = tile[2 * lane][mloc];
        float v1 = tile[2 * lane + 1][mloc];
        const size_t ob = ((size_t)m * NN + k0) >> 1;   // u32 index
        __half h0, l0, h1, l1;
        hsplit(v0, h0, l0); hsplit(v1, h1, l1);
        ((u32*)g_m2B_hi)[ob + lane] = pkh2(h0, h1);
        ((u32*)g_m2B_lo)[ob + lane] = pkh2(l0, l1);
        ((u32*)g_m2A_hi)[ob + lane] =
            pkh2(__float2half_rn(v0 * dv.x), __float2half_rn(v1 * dv.y));
    }
}

// =====================  fp16 2-term tensor-core GEMM, SYMMETRIC (triangular tiles)  ========
// M = A*(Bhi+Blo); which==0: oscale=1 (adjAv); which==1: oscale=256 (adjAe, undo dv scale)
#define KB 32
#define STG_BYTES 24576          // A 8K | Bhi 8K | Blo 8K
#define NSTAGE 3
#define SMEM_DYN (NSTAGE * STG_BYTES)
#define TP 129                   // transpose pitch (floats)

__device__ __forceinline__ void stage_load(u32 st0, int s,
        const __half* __restrict__ A,
        const __half* __restrict__ Bhi, const __half* __restrict__ Blo,
        int K, int m0, int n0, int k0, int tid) {
    u32 base = st0 + s * STG_BYTES;
#pragma unroll
    for (int i = 0; i < 4; i++) {
        int id = tid + i * 128;                // 0..511
        int r = id >> 2, c = id & 3;           // 128 rows x 4 16B-chunks
        u32 so = (u32)(r * 64 + ((c ^ (r & 3)) << 4));
        size_t gA = (size_t)(m0 + r) * K + k0 + c * 8;
        size_t gB = (size_t)(n0 + r) * K + k0 + c * 8;
        cp16(base + so, A + gA);
        cp16(base + 8192 + so, Bhi + gB);
        cp16(base + 16384 + so, Blo + gB);
    }
    asm volatile("cp.async.commit_group;" ::: "memory");
}

__global__ __launch_bounds__(128, 2) void k_mult_mma(int which, const float* __restrict__ adj) {
    extern __shared__ char smem[];
    const __half *A, *Bhi, *Blo;
    float* C;
    int K, ncols;
    float oscale;
    if (which == 0) {
        A = g_m1A_hi; Bhi = g_m1B_hi; Blo = g_m1B_lo;
        C = g_adjAv; K = NE; ncols = NN; oscale = 1.0f;
    } else {
        A = g_m2A_hi; Bhi = g_m2B_hi; Blo = g_m2B_lo;
        C = g_adjAe; K = NN; ncols = NE; oscale = DV_UNSCALE;
    }
    // triangular tile decode: t -> (bi >= bj)
    const int t = blockIdx.x;
    int bi = (int)((sqrtf(8.0f * (float)t + 1.0f) - 1.0f) * 0.5f);
    while ((bi + 1) * (bi + 2) / 2 <= t) bi++;
    while (bi * (bi + 1) / 2 > t) bi--;
    const int bj = t - bi * (bi + 1) / 2;
    const int m0 = bi * 128, n0 = bj * 128;
    const bool diagtile = (bi == bj);

    const u32 st0 = smem_u32(smem);
    const int tid = threadIdx.x;
    const int lane = tid & 31, wid = tid >> 5;
    const int wm = wid >> 1, wn = wid & 1;          // 2 x 2 warp grid, 64x64 tiles
    const int nk = K / KB;

    float acc[4][8][4];
#pragma unroll
    for (int i = 0; i < 4; i++)
#pragma unroll
        for (int j = 0; j < 8; j++)
#pragma unroll
            for (int q = 0; q < 4; q++) acc[i][j][q] = 0.f;

    stage_load(st0, 0, A, Bhi, Blo, K, m0, n0, 0, tid);
    stage_load(st0, 1, A, Bhi, Blo, K, m0, n0, KB, tid);

    const u32 arow = (u32)(wm * 64 + (lane & 15));
    const u32 brow = (u32)(wn * 64 + (lane & 15));
    const u32 asw = arow & 3, bsw = brow & 3;

    for (int kt = 0; kt < nk; kt++) {
        const int s = kt % NSTAGE;
        if (kt + 1 < nk) asm volatile("cp.async.wait_group 1;" ::: "memory");
        else             asm volatile("cp.async.wait_group 0;" ::: "memory");
        __syncthreads();
        if (kt + 2 < nk)
            stage_load(st0, (kt + 2) % NSTAGE, A, Bhi, Blo, K, m0, n0, (kt + 2) * KB, tid);

        const u32 base = st0 + s * STG_BYTES;
#pragma unroll
        for (int ks = 0; ks < 2; ks++) {
            const u32 cb = (u32)(ks * 2) + (u32)(lane >> 4);
            u32 Bh[8][2], Bl[8][2];
            const u32 boff = base + 8192 + brow * 64 + ((cb ^ bsw) << 4);
#pragma unroll
            for (int nip = 0; nip < 4; nip++) {
                u32 tr[4];
                LDSM4(tr, boff + nip * 1024);
                Bh[2 * nip][0] = tr[0]; Bh[2 * nip][1] = tr[2];
                Bh[2 * nip + 1][0] = tr[1]; Bh[2 * nip + 1][1] = tr[3];
                LDSM4(tr, boff + 8192 + nip * 1024);
                Bl[2 * nip][0] = tr[0]; Bl[2 * nip][1] = tr[2];
                Bl[2 * nip + 1][0] = tr[1]; Bl[2 * nip + 1][1] = tr[3];
            }
            const u32 aoff = base + arow * 64 + ((cb ^ asw) << 4);
#pragma unroll
            for (int mi = 0; mi < 4; mi++) {
                u32 ah[4];
                LDSM4(ah, aoff + mi * 1024);
#pragma unroll
                for (int ni = 0; ni < 8; ni++) {
                    MMA_F16(acc[mi][ni], ah, Bh[ni]);
                    MMA_F16(acc[mi][ni], ah, Bl[ni]);
                }
            }
        }
        __syncthreads();
    }

    // ---------- epilogue ----------
    float* stg = (float*)smem;                         // 128 x TP floats (transpose staging)
    u32* scm = (u32*)(smem + 128 * TP * 4);            // 128 u32 colmax (direct block)
    if (which == 1 && tid < 128) scm[tid] = 0u;
    __syncthreads();

    u32 kmax[8][2];
#pragma unroll
    for (int ni = 0; ni < 8; ni++) { kmax[ni][0] = 0u; kmax[ni][1] = 0u; }

#pragma unroll
    for (int mi = 0; mi < 4; mi++) {
#pragma unroll
        for (int h = 0; h < 2; h++) {
            const int row_l = wm * 64 + mi * 16 + (lane >> 2) + h * 8;
            const int row_g = m0 + row_l;
            const size_t rb = (size_t)row_g * ncols;
#pragma unroll
            for (int ni = 0; ni < 8; ni++) {
                const int col_l = wn * 64 + ni * 8 + (lane & 3) * 2;
                const int col_g = n0 + col_l;
                float v0 = acc[mi][ni][h * 2] * oscale;
                float v1 = acc[mi][ni][h * 2 + 1] * oscale;
                if (diagtile) {
                    if (row_g == col_g) v0 = 1.0f;
                    if (row_g == col_g + 1) v1 = 1.0f;
                } else {
                    stg[row_l * TP + col_l] = v0;
                    stg[row_l * TP + col_l + 1] = v1;
                }
                const float2 a = *(const float2*)(adj + rb + col_g);
                float w0 = v0 * a.x, w1 = v1 * a.y;
                *(float2*)(C + rb + col_g) = make_float2(w0, w1);
                if (which == 1) {
                    kmax[ni][0] = max(kmax[ni][0], fkey(w0));
                    kmax[ni][1] = max(kmax[ni][1], fkey(w1));
                }
            }
        }
    }
    if (which == 1) {
#pragma unroll
        for (int ni = 0; ni < 8; ni++) {
            const int cl = wn * 64 + ni * 8 + (lane & 3) * 2;
            atomicMax(scm + cl, kmax[ni][0]);
            atomicMax(scm + cl + 1, kmax[ni][1]);
        }
    }
    __syncthreads();
    if (which == 1 && tid < 128) atomicMax(g_cmaxu + n0 + tid, scm[tid]);

    // mirror block: C[n0+c][m0+r] = M[r][c] * adj[n0+c][m0+r]
    if (!diagtile) {
        u32 kloc[4] = {0u, 0u, 0u, 0u};
        for (int cc = 0; cc < 32; cc++) {
            const int c = wid * 32 + cc;
            const size_t orow = (size_t)(n0 + c) * ncols + m0;
#pragma unroll
            for (int ch = 0; ch < 4; ch++) {
                const int r = ch * 32 + lane;
                float v = stg[r * TP + c];
                float w = v * adj[orow + r];
                C[orow + r] = w;
                if (which == 1) kloc[ch] = max(kloc[ch], fkey(w));
            }
        }
        if (which == 1) {
#pragma unroll
            for (int ch = 0; ch < 4; ch++)
                atomicMax(g_cmaxu + m0 + ch * 32 + lane, kloc[ch]);
        }
    }
}

// =====================  Hv_out = adjAv @ HW + b_v  =====================
__global__ __launch_bounds__(256) void k_hv(const float* __restrict__ bv, float* __restrict__ out) {
    __shared__ __align__(16) float As[32 * 32];
    __shared__ __align__(16) float Bs[32 * 64];
    const int tid = threadIdx.x;
    const int tx = tid & 15, ty = tid >> 4;
    const int m0 = blockIdx.x * 32;
    const int arow = tid >> 3, ac4 = (tid & 7) * 4;
    const int brow = tid >> 4, bc4 = (tid & 15) * 4;
    float acc[2][4] = {{0, 0, 0, 0}, {0, 0, 0, 0}};
    for (int k0 = 0; k0 < NN; k0 += 32) {
        float4 fa = *(const float4*)(g_adjAv + (m0 + arow) * NN + k0 + ac4);
        float4 fb0 = *(const float4*)(g_HW + (k0 + brow) * DVO + bc4);
        float4 fb1 = *(const float4*)(g_HW + (k0 + brow + 16) * DVO + bc4);
        __syncthreads();
        As[(ac4 + 0) * 32 + arow] = fa.x; As[(ac4 + 1) * 32 + arow] = fa.y;
        As[(ac4 + 2) * 32 + arow] = fa.z; As[(ac4 + 3) * 32 + arow] = fa.w;
        *(float4*)(Bs + brow * 64 + bc4) = fb0;
        *(float4*)(Bs + (brow + 16) * 64 + bc4) = fb1;
        __syncthreads();
#pragma unroll
        for (int kk = 0; kk < 32; kk++) {
            float a0 = As[kk * 32 + ty * 2];
            float a1 = As[kk * 32 + ty * 2 + 1];
            float4 b = *(const float4*)(Bs + kk * 64 + tx * 4);
            acc[0][0] += a0 * b.x; acc[0][1] += a0 * b.y; acc[0][2] += a0 * b.z; acc[0][3] += a0 * b.w;
            acc[1][0] += a1 * b.x; acc[1][1] += a1 * b.y; acc[1][2] += a1 * b.z; acc[1][3] += a1 * b.w;
        }
    }
    float4 bb = *(const float4*)(bv + tx * 4);
#pragma unroll
    for (int r = 0; r < 2; r++) {
        int row = m0 + ty * 2 + r;
        *(float4*)(out + row * DVO + tx * 4) =
            make_float4(acc[r][0] + bb.x, acc[r][1] + bb.y, acc[r][2] + bb.z, acc[r][3] + bb.w);
    }
}

__global__ void k_dv(const float* __restrict__ Hv, const float* __restrict__ pe) {
    int w = (blockIdx.x * blockDim.x + threadIdx.x) >> 5;
    int lane = threadIdx.x & 31;
    float s = Hv[w * DVO + lane] * pe[lane] + Hv[w * DVO + 32 + lane] * pe[32 + lane];
#pragma unroll
    for (int o = 16; o > 0; o >>= 1) s += __shfl_down_sync(0xffffffffu, s, o);
    if (lane == 0) g_dv[w] = s;
}

// finalize colmax from keys, fold 1/(max+1e-10) into HeW -> HeWs
__global__ void k_cmax2() {
    int col = blockIdx.x * 256 + threadIdx.x;
    u32 k = g_cmaxu[col];
    u32 b = (k & 0x80000000u) ? (k ^ 0x80000000u) : ~k;
    float m = __uint_as_float(b);
    float inv = 1.0f / (m + 1e-10f);
#pragma unroll
    for (int c = 0; c < DEO; c++) g_HeWs[col * DEO + c] = g_HeW[col * DEO + c] * inv;
}

__global__ __launch_bounds__(256) void k_he(const float* __restrict__ be, float* __restrict__ out) {
    __shared__ __align__(16) float As[64 * 64];
    __shared__ __align__(16) float Bs[64 * 16];
    const int tid = threadIdx.x;
    const int c = tid & 15, tr = tid >> 4;
    const int m0 = blockIdx.x * 64;
    const int lc4 = (tid & 15) * 4;
    float acc[4] = {0, 0, 0, 0};
    for (int k0 = 0; k0 < NE; k0 += 64) {
        float4 ra[4]; float rb[4];
#pragma unroll
        for (int q = 0; q < 4; q++) {
            int row = tr + q * 16;
            ra[q] = *(const float4*)(g_adjAe + (size_t)(m0 + row) * NE + k0 + lc4);
            rb[q] = g_HeWs[(k0 + row) * DEO + c];
        }
        __syncthreads();
#pragma unroll
        for (int q = 0; q < 4; q++) {
            int row = tr + q * 16;
            *(float4*)(As + row * 64 + lc4) = ra[q];
            Bs[row * 16 + c] = rb[q];
        }
        __syncthreads();
#pragma unroll 8
        for (int kk = 0; kk < 64; kk++) {
            float b = Bs[kk * 16 + c];
            acc[0] += As[(0 * 16 + tr) * 64 + kk] * b;
            acc[1] += As[(1 * 16 + tr) * 64 + kk] * b;
            acc[2] += As[(2 * 16 + tr) * 64 + kk] * b;
            acc[3] += As[(3 * 16 + tr) * 64 + kk] * b;
        }
    }
    float bc = be[c];
#pragma unroll
    for (int q = 0; q < 4; q++)
        out[(m0 + q * 16 + tr) * DEO + c] = acc[q] + bc;
}

// =====================  launch  =====================
extern "C" void kernel_launch(void* const* d_in, const int* in_sizes, int n_in,
                              void* d_out, int out_size) {
    const float* H_v  = (const float*)d_in[0];
    const float* H_e  = (const float*)d_in[1];
    const float* adjv = (const float*)d_in[2];
    const float* adje = (const float*)d_in[3];
    const float* T    = (const float*)d_in[4];
    const float* W_v  = (const float*)d_in[5];
    const float* b_v  = (const float*)d_in[6];
    const float* p_v  = (const float*)d_in[7];
    const float* W_e  = (const float*)d_in[8];
    const float* b_e  = (const float*)d_in[9];
    const float* p_e  = (const float*)d_in[10];
    float* out = (float*)d_out;
    (void)in_sizes; (void)n_in; (void)out_size;

    cudaFuncSetAttribute(k_mult_mma, cudaFuncAttributeMaxDynamicSharedMemorySize, SMEM_DYN);

    k_de<<<24, 256>>>(H_e, p_v);
    k_hew<<<384, 256>>>(H_e, W_e);
    k_hw<<<512, 256>>>(H_v, W_v);
    k_cinit<<<24, 256>>>();
    k_split1<<<12288, 256>>>(T);
    k_mult_mma<<<136, 128, SMEM_DYN>>>(0, adjv);    // adjAv, fp16 2-term, triangular
    k_hv<<<64, 256>>>(b_v, out);
    k_dv<<<256, 256>>>(out, p_e);
    k_split2<<<dim3(192, 32), dim3(32, 8)>>>(T);
    k_mult_mma<<<1176, 128, SMEM_DYN>>>(1, adje);   // adjAe, fp16 2-term, triangular
    k_cmax2<<<24, 256>>>();
    k_he<<<96, 256>>>(b_e, out + NN * DVO);
}

// round 11
// speedup vs baseline: 2.2848x; 1.0485x over previous
#include <cuda_runtime.h>
#include <cuda_fp16.h>
#include <cstdint>

typedef unsigned int u32;
typedef unsigned long long u64;

#define NN 2048
#define NE 6144
#define KDV 128
#define DVO 64
#define DEI 16
#define DEO 16

#define DV_SCALE (1.0f / 256.0f)
#define DV_UNSCALE 256.0f

// =====================  scratch  =====================
__device__ __align__(16) __half g_m1A_hi[NN * NE];      // fp16(T * d_e[col])
__device__ __align__(16) __half g_m1B_hi[NN * NE];
__device__ __align__(16) __half g_m1B_lo[NN * NE];
__device__ __align__(16) __half g_m2A_hi[NE * NN];      // fp16(T^T * d_v * 2^-8)
__device__ __align__(16) __half g_m2B_hi[NE * NN];
__device__ __align__(16) __half g_m2B_lo[NE * NN];
__device__ __align__(16) float g_adjAv[NN * NN];
__device__ __align__(16) float g_adjAe[(size_t)NE * NE];
__device__ __align__(16) float g_HW[NN * DVO];
__device__ __align__(16) float g_hvp[4][NN * DVO];      // k_hv split-K partials
__device__ __align__(16) float g_HeW[NE * DEO];
__device__ __align__(16) float g_HeWs[NE * DEO];
__device__ __align__(16) float g_de[NE];
__device__ __align__(16) float g_dv[NN];
__device__ u32 g_cmaxu[NE];

// =====================  helpers  =====================
__device__ __forceinline__ u32 smem_u32(const void* p) {
    u32 a;
    asm("{ .reg .u64 t; cvta.to.shared.u64 t, %1; cvt.u32.u64 %0, t; }" : "=r"(a) : "l"(p));
    return a;
}

__device__ __forceinline__ void cp16(u32 saddr, const __half* gptr) {
    asm volatile("cp.async.cg.shared.global [%0], [%1], 16;"
                 :: "r"(saddr), "l"(__cvta_generic_to_global(gptr)) : "memory");
}

#define LDSM4(r, addr)                                                          \
    asm volatile("ldmatrix.sync.aligned.m8n8.x4.shared.b16 {%0,%1,%2,%3}, [%4];" \
                 : "=r"((r)[0]), "=r"((r)[1]), "=r"((r)[2]), "=r"((r)[3]) : "r"(addr))

#define MMA_F16(d, a, b)                                                         \
    asm volatile("mma.sync.aligned.m16n8k16.row.col.f32.f16.f16.f32 "            \
                 "{%0,%1,%2,%3},{%4,%5,%6,%7},{%8,%9},{%0,%1,%2,%3};"            \
                 : "+f"((d)[0]), "+f"((d)[1]), "+f"((d)[2]), "+f"((d)[3])        \
                 : "r"((a)[0]), "r"((a)[1]), "r"((a)[2]), "r"((a)[3]),           \
                   "r"((b)[0]), "r"((b)[1]))

__device__ __forceinline__ void hsplit(float x, __half& hi, __half& lo) {
    hi = __float2half_rn(x);
    lo = __float2half_rn(x - __half2float(hi));
}
__device__ __forceinline__ u32 pkh2(__half a, __half b) {
    __half2 h = __halves2half2(a, b);
    return *(u32*)&h;
}
__device__ __forceinline__ u32 fkey(float f) {
    u32 b = __float_as_uint(f);
    return (b & 0x80000000u) ? ~b : (b | 0x80000000u);
}

// =====================  tiny prologue kernels  =====================
__global__ void k_de(const float* __restrict__ He, const float* __restrict__ pv) {
    int e = blockIdx.x * 256 + threadIdx.x;
    float s = 0.f;
#pragma unroll
    for (int k = 0; k < DEI; k++) s += He[e * DEI + k] * pv[k];
    g_de[e] = s;
}

__global__ void k_hew(const float* __restrict__ He, const float* __restrict__ We) {
    int idx = blockIdx.x * 256 + threadIdx.x;
    int e = idx >> 4, c = idx & 15;
    float s = 0.f;
#pragma unroll
    for (int k = 0; k < DEI; k++) s += He[e * DEI + k] * We[k * DEO + c];
    g_HeW[idx] = s;
}

__global__ void k_hw(const float* __restrict__ Hv, const float* __restrict__ Wv) {
    int idx = blockIdx.x * 256 + threadIdx.x;
    int i = idx >> 6, c = idx & 63;
    float s = 0.f;
#pragma unroll 8
    for (int k = 0; k < KDV; k++) s += Hv[i * KDV + k] * Wv[k * DVO + c];
    g_HW[idx] = s;
}

__global__ void k_cinit() {
    g_cmaxu[blockIdx.x * 256 + threadIdx.x] = 0u;
}

// mult1 prep: B = T (hi/lo), A = fp16(T * d_e[col]). [NN][NE] K-major.
__global__ void k_split1(const float* __restrict__ T) {
    size_t i = (size_t)blockIdx.x * 256 + threadIdx.x;   // float4 index
    float4 t = ((const float4*)T)[i];
    int col = (int)((i * 4) % NE);
    float4 de = *(const float4*)(g_de + col);
    __half hx, lx, hy, ly, hz, lz, hw, lw;
    hsplit(t.x, hx, lx); hsplit(t.y, hy, ly); hsplit(t.z, hz, lz); hsplit(t.w, hw, lw);
    ((uint2*)g_m1B_hi)[i] = make_uint2(pkh2(hx, hy), pkh2(hz, hw));
    ((uint2*)g_m1B_lo)[i] = make_uint2(pkh2(lx, ly), pkh2(lz, lw));
    ((uint2*)g_m1A_hi)[i] = make_uint2(
        pkh2(__float2half_rn(t.x * de.x), __float2half_rn(t.y * de.y)),
        pkh2(__float2half_rn(t.z * de.z), __float2half_rn(t.w * de.w)));
}

// mult2 prep (transpose): B2[m][k] = T[k][m] (hi/lo); A2[m][k] = fp16(T[k][m]*d_v[k]*2^-8).
__global__ void k_split2(const float* __restrict__ T) {
    __shared__ float tile[64][33];
    const int m0 = blockIdx.x * 32, k0 = blockIdx.y * 64;
    const int tx = threadIdx.x, ty = threadIdx.y;     // (32, 8)
#pragma unroll
    for (int j = 0; j < 8; j++) {
        int r = ty + j * 8;
        tile[r][tx] = T[(size_t)(k0 + r) * NE + m0 + tx];
    }
    __syncthreads();
    const int lane = tx, w = ty;
    float2 dv = ((const float2*)(g_dv + k0))[lane];
    dv.x *= DV_SCALE; dv.y *= DV_SCALE;
#pragma unroll
    for (int q = 0; q < 4; q++) {
        const int mloc = w + 8 * q;
        const int m = m0 + mloc;
        float v0 = tile[2 * lane][mloc];
        float v1 = tile[2 * lane + 1][mloc];
        const size_t ob = ((size_t)m * NN + k0) >> 1;   // u32 index
        __half h0, l0, h1, l1;
        hsplit(v0, h0, l0); hsplit(v1, h1, l1);
        ((u32*)g_m2B_hi)[ob + lane] = pkh2(h0, h1);
        ((u32*)g_m2B_lo)[ob + lane] = pkh2(l0, l1);
        ((u32*)g_m2A_hi)[ob + lane] =
            pkh2(__float2half_rn(v0 * dv.x), __float2half_rn(v1 * dv.y));
    }
}

// =====================  fp16 2-term tensor-core GEMM, SYMMETRIC (triangular tiles)  ========
// M = A*(Bhi+Blo); which==0: oscale=1 (adjAv); which==1: oscale=256 (adjAe, undo dv scale)
#define KB 32
#define STG_BYTES 24576          // A 8K | Bhi 8K | Blo 8K
#define NSTAGE 3
#define SMEM_DYN (NSTAGE * STG_BYTES)
#define TP 129                   // transpose pitch (floats)

__device__ __forceinline__ void stage_load(u32 st0, int s,
        const __half* __restrict__ A,
        const __half* __restrict__ Bhi, const __half* __restrict__ Blo,
        int K, int m0, int n0, int k0, int tid) {
    u32 base = st0 + s * STG_BYTES;
#pragma unroll
    for (int i = 0; i < 4; i++) {
        int id = tid + i * 128;                // 0..511
        int r = id >> 2, c = id & 3;           // 128 rows x 4 16B-chunks
        u32 so = (u32)(r * 64 + ((c ^ (r & 3)) << 4));
        size_t gA = (size_t)(m0 + r) * K + k0 + c * 8;
        size_t gB = (size_t)(n0 + r) * K + k0 + c * 8;
        cp16(base + so, A + gA);
        cp16(base + 8192 + so, Bhi + gB);
        cp16(base + 16384 + so, Blo + gB);
    }
    asm volatile("cp.async.commit_group;" ::: "memory");
}

__global__ __launch_bounds__(128, 2) void k_mult_mma(int which, const float* __restrict__ adj) {
    extern __shared__ char smem[];
    const __half *A, *Bhi, *Blo;
    float* C;
    int K, ncols;
    float oscale;
    if (which == 0) {
        A = g_m1A_hi; Bhi = g_m1B_hi; Blo = g_m1B_lo;
        C = g_adjAv; K = NE; ncols = NN; oscale = 1.0f;
    } else {
        A = g_m2A_hi; Bhi = g_m2B_hi; Blo = g_m2B_lo;
        C = g_adjAe; K = NN; ncols = NE; oscale = DV_UNSCALE;
    }
    // triangular tile decode: t -> (bi >= bj)
    const int t = blockIdx.x;
    int bi = (int)((sqrtf(8.0f * (float)t + 1.0f) - 1.0f) * 0.5f);
    while ((bi + 1) * (bi + 2) / 2 <= t) bi++;
    while (bi * (bi + 1) / 2 > t) bi--;
    const int bj = t - bi * (bi + 1) / 2;
    const int m0 = bi * 128, n0 = bj * 128;
    const bool diagtile = (bi == bj);

    const u32 st0 = smem_u32(smem);
    const int tid = threadIdx.x;
    const int lane = tid & 31, wid = tid >> 5;
    const int wm = wid >> 1, wn = wid & 1;          // 2 x 2 warp grid, 64x64 tiles
    const int nk = K / KB;

    float acc[4][8][4];
#pragma unroll
    for (int i = 0; i < 4; i++)
#pragma unroll
        for (int j = 0; j < 8; j++)
#pragma unroll
            for (int q = 0; q < 4; q++) acc[i][j][q] = 0.f;

    stage_load(st0, 0, A, Bhi, Blo, K, m0, n0, 0, tid);
    stage_load(st0, 1, A, Bhi, Blo, K, m0, n0, KB, tid);

    const u32 arow = (u32)(wm * 64 + (lane & 15));
    const u32 brow = (u32)(wn * 64 + (lane & 15));
    const u32 asw = arow & 3, bsw = brow & 3;

    for (int kt = 0; kt < nk; kt++) {
        const int s = kt % NSTAGE;
        if (kt + 1 < nk) asm volatile("cp.async.wait_group 1;" ::: "memory");
        else             asm volatile("cp.async.wait_group 0;" ::: "memory");
        __syncthreads();
        if (kt + 2 < nk)
            stage_load(st0, (kt + 2) % NSTAGE, A, Bhi, Blo, K, m0, n0, (kt + 2) * KB, tid);

        const u32 base = st0 + s * STG_BYTES;
#pragma unroll
        for (int ks = 0; ks < 2; ks++) {
            const u32 cb = (u32)(ks * 2) + (u32)(lane >> 4);
            u32 Bh[8][2], Bl[8][2], Ah[4][4];
            const u32 boff = base + 8192 + brow * 64 + ((cb ^ bsw) << 4);
#pragma unroll
            for (int nip = 0; nip < 4; nip++) {
                u32 tr[4];
                LDSM4(tr, boff + nip * 1024);
                Bh[2 * nip][0] = tr[0]; Bh[2 * nip][1] = tr[2];
                Bh[2 * nip + 1][0] = tr[1]; Bh[2 * nip + 1][1] = tr[3];
                LDSM4(tr, boff + 8192 + nip * 1024);
                Bl[2 * nip][0] = tr[0]; Bl[2 * nip][1] = tr[2];
                Bl[2 * nip + 1][0] = tr[1]; Bl[2 * nip + 1][1] = tr[3];
            }
            const u32 aoff = base + arow * 64 + ((cb ^ asw) << 4);
#pragma unroll
            for (int mi = 0; mi < 4; mi++)
                LDSM4(Ah[mi], aoff + mi * 1024);
            // all Bhi terms, then all Blo terms: accumulator RAW distance 1 -> 32
#pragma unroll
            for (int mi = 0; mi < 4; mi++)
#pragma unroll
                for (int ni = 0; ni < 8; ni++)
                    MMA_F16(acc[mi][ni], Ah[mi], Bh[ni]);
#pragma unroll
            for (int mi = 0; mi < 4; mi++)
#pragma unroll
                for (int ni = 0; ni < 8; ni++)
                    MMA_F16(acc[mi][ni], Ah[mi], Bl[ni]);
        }
        __syncthreads();
    }

    // ---------- epilogue ----------
    float* stg = (float*)smem;                         // 128 x TP floats (transpose staging)
    u32* scm = (u32*)(smem + 128 * TP * 4);            // 128 u32 colmax (direct block)
    if (which == 1 && tid < 128) scm[tid] = 0u;
    __syncthreads();

    u32 kmax[8][2];
#pragma unroll
    for (int ni = 0; ni < 8; ni++) { kmax[ni][0] = 0u; kmax[ni][1] = 0u; }

#pragma unroll
    for (int mi = 0; mi < 4; mi++) {
#pragma unroll
        for (int h = 0; h < 2; h++) {
            const int row_l = wm * 64 + mi * 16 + (lane >> 2) + h * 8;
            const int row_g = m0 + row_l;
            const size_t rb = (size_t)row_g * ncols;
#pragma unroll
            for (int ni = 0; ni < 8; ni++) {
                const int col_l = wn * 64 + ni * 8 + (lane & 3) * 2;
                const int col_g = n0 + col_l;
                float v0 = acc[mi][ni][h * 2] * oscale;
                float v1 = acc[mi][ni][h * 2 + 1] * oscale;
                if (diagtile) {
                    if (row_g == col_g) v0 = 1.0f;
                    if (row_g == col_g + 1) v1 = 1.0f;
                } else {
                    stg[row_l * TP + col_l] = v0;
                    stg[row_l * TP + col_l + 1] = v1;
                }
                const float2 a = *(const float2*)(adj + rb + col_g);
                float w0 = v0 * a.x, w1 = v1 * a.y;
                *(float2*)(C + rb + col_g) = make_float2(w0, w1);
                if (which == 1) {
                    kmax[ni][0] = max(kmax[ni][0], fkey(w0));
                    kmax[ni][1] = max(kmax[ni][1], fkey(w1));
                }
            }
        }
    }
    if (which == 1) {
#pragma unroll
        for (int ni = 0; ni < 8; ni++) {
            const int cl = wn * 64 + ni * 8 + (lane & 3) * 2;
            atomicMax(scm + cl, kmax[ni][0]);
            atomicMax(scm + cl + 1, kmax[ni][1]);
        }
    }
    __syncthreads();
    if (which == 1 && tid < 128) atomicMax(g_cmaxu + n0 + tid, scm[tid]);

    // mirror block: C[n0+c][m0+r] = M[r][c] * adj[n0+c][m0+r]
    if (!diagtile) {
        u32 kloc[4] = {0u, 0u, 0u, 0u};
        for (int cc = 0; cc < 32; cc++) {
            const int c = wid * 32 + cc;
            const size_t orow = (size_t)(n0 + c) * ncols + m0;
#pragma unroll
            for (int ch = 0; ch < 4; ch++) {
                const int r = ch * 32 + lane;
                float v = stg[r * TP + c];
                float w = v * adj[orow + r];
                C[orow + r] = w;
                if (which == 1) kloc[ch] = max(kloc[ch], fkey(w));
            }
        }
        if (which == 1) {
#pragma unroll
            for (int ch = 0; ch < 4; ch++)
                atomicMax(g_cmaxu + m0 + ch * 32 + lane, kloc[ch]);
        }
    }
}

// =====================  Hv partials: g_hvp[kc] = adjAv[:, kc*512:(kc+1)*512] @ HW  ======
__global__ __launch_bounds__(256) void k_hv(float* __restrict__ dummy) {
    __shared__ __align__(16) float As[32 * 32];
    __shared__ __align__(16) float Bs[32 * 64];
    const int tid = threadIdx.x;
    const int tx = tid & 15, ty = tid >> 4;
    const int m0 = blockIdx.x * 32;
    const int kc = blockIdx.y;
    const int arow = tid >> 3, ac4 = (tid & 7) * 4;
    const int brow = tid >> 4, bc4 = (tid & 15) * 4;
    float acc[2][4] = {{0, 0, 0, 0}, {0, 0, 0, 0}};
    for (int k0 = kc * 512; k0 < (kc + 1) * 512; k0 += 32) {
        float4 fa = *(const float4*)(g_adjAv + (m0 + arow) * NN + k0 + ac4);
        float4 fb0 = *(const float4*)(g_HW + (k0 + brow) * DVO + bc4);
        float4 fb1 = *(const float4*)(g_HW + (k0 + brow + 16) * DVO + bc4);
        __syncthreads();
        As[(ac4 + 0) * 32 + arow] = fa.x; As[(ac4 + 1) * 32 + arow] = fa.y;
        As[(ac4 + 2) * 32 + arow] = fa.z; As[(ac4 + 3) * 32 + arow] = fa.w;
        *(float4*)(Bs + brow * 64 + bc4) = fb0;
        *(float4*)(Bs + (brow + 16) * 64 + bc4) = fb1;
        __syncthreads();
#pragma unroll
        for (int kk = 0; kk < 32; kk++) {
            float a0 = As[kk * 32 + ty * 2];
            float a1 = As[kk * 32 + ty * 2 + 1];
            float4 b = *(const float4*)(Bs + kk * 64 + tx * 4);
            acc[0][0] += a0 * b.x; acc[0][1] += a0 * b.y; acc[0][2] += a0 * b.z; acc[0][3] += a0 * b.w;
            acc[1][0] += a1 * b.x; acc[1][1] += a1 * b.y; acc[1][2] += a1 * b.z; acc[1][3] += a1 * b.w;
        }
    }
#pragma unroll
    for (int r = 0; r < 2; r++) {
        int row = m0 + ty * 2 + r;
        *(float4*)(g_hvp[kc] + row * DVO + tx * 4) =
            make_float4(acc[r][0], acc[r][1], acc[r][2], acc[r][3]);
    }
}

// reduce partials + bias -> out
__global__ void k_hvred(const float* __restrict__ bv, float* __restrict__ out) {
    int idx = blockIdx.x * 256 + threadIdx.x;          // 131072
    int c = idx & 63;
    float s = bv[c] + g_hvp[0][idx] + g_hvp[1][idx] + g_hvp[2][idx] + g_hvp[3][idx];
    out[idx] = s;
}

__global__ void k_dv(const float* __restrict__ Hv, const float* __restrict__ pe) {
    int w = (blockIdx.x * blockDim.x + threadIdx.x) >> 5;
    int lane = threadIdx.x & 31;
    float s = Hv[w * DVO + lane] * pe[lane] + Hv[w * DVO + 32 + lane] * pe[32 + lane];
#pragma unroll
    for (int o = 16; o > 0; o >>= 1) s += __shfl_down_sync(0xffffffffu, s, o);
    if (lane == 0) g_dv[w] = s;
}

// finalize colmax from keys, fold 1/(max+1e-10) into HeW -> HeWs
__global__ void k_cmax2() {
    int col = blockIdx.x * 256 + threadIdx.x;
    u32 k = g_cmaxu[col];
    u32 b = (k & 0x80000000u) ? (k ^ 0x80000000u) : ~k;
    float m = __uint_as_float(b);
    float inv = 1.0f / (m + 1e-10f);
#pragma unroll
    for (int c = 0; c < DEO; c++) g_HeWs[col * DEO + c] = g_HeW[col * DEO + c] * inv;
}

__global__ __launch_bounds__(256) void k_he(const float* __restrict__ be, float* __restrict__ out) {
    __shared__ __align__(16) float As[64 * 64];
    __shared__ __align__(16) float Bs[64 * 16];
    const int tid = threadIdx.x;
    const int c = tid & 15, tr = tid >> 4;
    const int m0 = blockIdx.x * 64;
    const int lc4 = (tid & 15) * 4;
    float acc[4] = {0, 0, 0, 0};
    for (int k0 = 0; k0 < NE; k0 += 64) {
        float4 ra[4]; float rb[4];
#pragma unroll
        for (int q = 0; q < 4; q++) {
            int row = tr + q * 16;
            ra[q] = *(const float4*)(g_adjAe + (size_t)(m0 + row) * NE + k0 + lc4);
            rb[q] = g_HeWs[(k0 + row) * DEO + c];
        }
        __syncthreads();
#pragma unroll
        for (int q = 0; q < 4; q++) {
            int row = tr + q * 16;
            *(float4*)(As + row * 64 + lc4) = ra[q];
            Bs[row * 16 + c] = rb[q];
        }
        __syncthreads();
#pragma unroll 8
        for (int kk = 0; kk < 64; kk++) {
            float b = Bs[kk * 16 + c];
            acc[0] += As[(0 * 16 + tr) * 64 + kk] * b;
            acc[1] += As[(1 * 16 + tr) * 64 + kk] * b;
            acc[2] += As[(2 * 16 + tr) * 64 + kk] * b;
            acc[3] += As[(3 * 16 + tr) * 64 + kk] * b;
        }
    }
    float bc = be[c];
#pragma unroll
    for (int q = 0; q < 4; q++)
        out[(m0 + q * 16 + tr) * DEO + c] = acc[q] + bc;
}

// =====================  launch  =====================
extern "C" void kernel_launch(void* const* d_in, const int* in_sizes, int n_in,
                              void* d_out, int out_size) {
    const float* H_v  = (const float*)d_in[0];
    const float* H_e  = (const float*)d_in[1];
    const float* adjv = (const float*)d_in[2];
    const float* adje = (const float*)d_in[3];
    const float* T    = (const float*)d_in[4];
    const float* W_v  = (const float*)d_in[5];
    const float* b_v  = (const float*)d_in[6];
    const float* p_v  = (const float*)d_in[7];
    const float* W_e  = (const float*)d_in[8];
    const float* b_e  = (const float*)d_in[9];
    const float* p_e  = (const float*)d_in[10];
    float* out = (float*)d_out;
    (void)in_sizes; (void)n_in; (void)out_size;

    cudaFuncSetAttribute(k_mult_mma, cudaFuncAttributeMaxDynamicSharedMemorySize, SMEM_DYN);

    k_de<<<24, 256>>>(H_e, p_v);
    k_hew<<<384, 256>>>(H_e, W_e);
    k_hw<<<512, 256>>>(H_v, W_v);
    k_cinit<<<24, 256>>>();
    k_split1<<<12288, 256>>>(T);
    k_mult_mma<<<136, 128, SMEM_DYN>>>(0, adjv);    // adjAv, fp16 2-term, triangular
    k_hv<<<dim3(64, 4), 256>>>(out);                // split-K partials
    k_hvred<<<512, 256>>>(b_v, out);                // reduce + bias -> Hv_out
    k_dv<<<256, 256>>>(out, p_e);
    k_split2<<<dim3(192, 32), dim3(32, 8)>>>(T);
    k_mult_mma<<<1176, 128, SMEM_DYN>>>(1, adje);   // adjAe, fp16 2-term, triangular
    k_cmax2<<<24, 256>>>();
    k_he<<<96, 256>>>(b_e, out + NN * DVO);
}

// round 12
// speedup vs baseline: 2.6330x; 1.1524x over previous
#include <cuda_runtime.h>
#include <cuda_fp16.h>
#include <cstdint>

typedef unsigned int u32;
typedef unsigned long long u64;

#define NN 2048
#define NE 6144
#define KDV 128
#define DVO 64
#define DEI 16
#define DEO 16

#define DV_SCALE (1.0f / 256.0f)
#define DV_UNSCALE 256.0f

// =====================  scratch  =====================
__device__ __align__(16) __half g_m1A[NN * NE];         // fp16(T * d_e[col])
__device__ __align__(16) __half g_m1B[NN * NE];         // fp16(T)
__device__ __align__(16) __half g_m2A[NE * NN];         // fp16(T^T * d_v * 2^-8)
__device__ __align__(16) __half g_m2B_hi[NE * NN];
__device__ __align__(16) __half g_m2B_lo[NE * NN];
__device__ __align__(16) float g_adjAv[NN * NN];
__device__ __align__(16) float g_adjAe[(size_t)NE * NE];
__device__ __align__(16) float g_HW[NN * DVO];
__device__ __align__(16) float g_hvp[4][NN * DVO];      // k_hv split-K partials
__device__ __align__(16) float g_HeW[NE * DEO];
__device__ __align__(16) float g_HeWs[NE * DEO];
__device__ __align__(16) float g_de[NE];
__device__ __align__(16) float g_dv[NN];
__device__ u32 g_cmaxu[NE];

// =====================  helpers  =====================
__device__ __forceinline__ u32 smem_u32(const void* p) {
    u32 a;
    asm("{ .reg .u64 t; cvta.to.shared.u64 t, %1; cvt.u32.u64 %0, t; }" : "=r"(a) : "l"(p));
    return a;
}

__device__ __forceinline__ void cp16(u32 saddr, const __half* gptr) {
    asm volatile("cp.async.cg.shared.global [%0], [%1], 16;"
                 :: "r"(saddr), "l"(__cvta_generic_to_global(gptr)) : "memory");
}

#define LDSM4(r, addr)                                                          \
    asm volatile("ldmatrix.sync.aligned.m8n8.x4.shared.b16 {%0,%1,%2,%3}, [%4];" \
                 : "=r"((r)[0]), "=r"((r)[1]), "=r"((r)[2]), "=r"((r)[3]) : "r"(addr))

#define MMA_F16(d, a, b)                                                         \
    asm volatile("mma.sync.aligned.m16n8k16.row.col.f32.f16.f16.f32 "            \
                 "{%0,%1,%2,%3},{%4,%5,%6,%7},{%8,%9},{%0,%1,%2,%3};"            \
                 : "+f"((d)[0]), "+f"((d)[1]), "+f"((d)[2]), "+f"((d)[3])        \
                 : "r"((a)[0]), "r"((a)[1]), "r"((a)[2]), "r"((a)[3]),           \
                   "r"((b)[0]), "r"((b)[1]))

__device__ __forceinline__ void hsplit(float x, __half& hi, __half& lo) {
    hi = __float2half_rn(x);
    lo = __float2half_rn(x - __half2float(hi));
}
__device__ __forceinline__ u32 pkh2(__half a, __half b) {
    __half2 h = __halves2half2(a, b);
    return *(u32*)&h;
}
__device__ __forceinline__ u32 fkey(float f) {
    u32 b = __float_as_uint(f);
    return (b & 0x80000000u) ? ~b : (b | 0x80000000u);
}

// =====================  tiny prologue kernels  =====================
__global__ void k_de(const float* __restrict__ He, const float* __restrict__ pv) {
    int e = blockIdx.x * 256 + threadIdx.x;
    float s = 0.f;
#pragma unroll
    for (int k = 0; k < DEI; k++) s += He[e * DEI + k] * pv[k];
    g_de[e] = s;
}

__global__ void k_hew(const float* __restrict__ He, const float* __restrict__ We) {
    int idx = blockIdx.x * 256 + threadIdx.x;
    int e = idx >> 4, c = idx & 15;
    float s = 0.f;
#pragma unroll
    for (int k = 0; k < DEI; k++) s += He[e * DEI + k] * We[k * DEO + c];
    g_HeW[idx] = s;
}

__global__ void k_hw(const float* __restrict__ Hv, const float* __restrict__ Wv) {
    int idx = blockIdx.x * 256 + threadIdx.x;
    int i = idx >> 6, c = idx & 63;
    float s = 0.f;
#pragma unroll 8
    for (int k = 0; k < KDV; k++) s += Hv[i * KDV + k] * Wv[k * DVO + c];
    g_HW[idx] = s;
}

__global__ void k_cinit() {
    g_cmaxu[blockIdx.x * 256 + threadIdx.x] = 0u;
}

// mult1 prep: B = fp16(T), A = fp16(T * d_e[col]). [NN][NE] K-major.
__global__ void k_split1(const float* __restrict__ T) {
    size_t i = (size_t)blockIdx.x * 256 + threadIdx.x;   // float4 index
    float4 t = ((const float4*)T)[i];
    int col = (int)((i * 4) % NE);
    float4 de = *(const float4*)(g_de + col);
    ((uint2*)g_m1B)[i] = make_uint2(
        pkh2(__float2half_rn(t.x), __float2half_rn(t.y)),
        pkh2(__float2half_rn(t.z), __float2half_rn(t.w)));
    ((uint2*)g_m1A)[i] = make_uint2(
        pkh2(__float2half_rn(t.x * de.x), __float2half_rn(t.y * de.y)),
        pkh2(__float2half_rn(t.z * de.z), __float2half_rn(t.w * de.w)));
}

// mult2 prep (transpose): B2[m][k] = T[k][m] (hi/lo); A2[m][k] = fp16(T[k][m]*d_v[k]*2^-8).
__global__ void k_split2(const float* __restrict__ T) {
    __shared__ float tile[64][33];
    const int m0 = blockIdx.x * 32, k0 = blockIdx.y * 64;
    const int tx = threadIdx.x, ty = threadIdx.y;     // (32, 8)
#pragma unroll
    for (int j = 0; j < 8; j++) {
        int r = ty + j * 8;
        tile[r][tx] = T[(size_t)(k0 + r) * NE + m0 + tx];
    }
    __syncthreads();
    const int lane = tx, w = ty;
    float2 dv = ((const float2*)(g_dv + k0))[lane];
    dv.x *= DV_SCALE; dv.y *= DV_SCALE;
#pragma unroll
    for (int q = 0; q < 4; q++) {
        const int mloc = w + 8 * q;
        const int m = m0 + mloc;
        float v0 = tile[2 * lane][mloc];
        float v1 = tile[2 * lane + 1][mloc];
        const size_t ob = ((size_t)m * NN + k0) >> 1;   // u32 index
        __half h0, l0, h1, l1;
        hsplit(v0, h0, l0); hsplit(v1, h1, l1);
        ((u32*)g_m2B_hi)[ob + lane] = pkh2(h0, h1);
        ((u32*)g_m2B_lo)[ob + lane] = pkh2(l0, l1);
        ((u32*)g_m2A)[ob + lane] =
            pkh2(__float2half_rn(v0 * dv.x), __float2half_rn(v1 * dv.y));
    }
}

// =====================  fp16 tensor-core GEMM, SYMMETRIC (triangular tiles)  ========
// which==0: 1-term M = A*B,           oscale=1   (adjAv)
// which==1: 2-term M = A*(Bhi+Blo),   oscale=256 (adjAe, undo dv scale)
#define KB 64
#define STG_BYTES 49152          // A 16K | Bhi 16K | Blo 16K
#define SMEM_DYN (2 * STG_BYTES)
#define TP 129                   // transpose pitch (floats)

__device__ __forceinline__ void stage_load(u32 st0, int s,
        const __half* __restrict__ A,
        const __half* __restrict__ Bhi, const __half* __restrict__ Blo,
        int K, int m0, int n0, int k0, int tid, bool loadBlo) {
    u32 base = st0 + s * STG_BYTES;
#pragma unroll
    for (int i = 0; i < 8; i++) {
        int id = tid + i * 128;                // 0..1023
        int r = id >> 3, c = id & 7;           // 128 rows x 8 16B-chunks
        u32 so = (u32)(r * 128 + ((c ^ (r & 7)) << 4));
        size_t gA = (size_t)(m0 + r) * K + k0 + c * 8;
        size_t gB = (size_t)(n0 + r) * K + k0 + c * 8;
        cp16(base + so, A + gA);
        cp16(base + 16384 + so, Bhi + gB);
        if (loadBlo) cp16(base + 32768 + so, Blo + gB);
    }
    asm volatile("cp.async.commit_group;" ::: "memory");
}

__global__ __launch_bounds__(128, 2) void k_mult_mma(int which, const float* __restrict__ adj) {
    extern __shared__ char smem[];
    const __half *A, *Bhi, *Blo;
    float* C;
    int K, ncols;
    float oscale;
    if (which == 0) {
        A = g_m1A; Bhi = g_m1B; Blo = g_m1B;
        C = g_adjAv; K = NE; ncols = NN; oscale = 1.0f;
    } else {
        A = g_m2A; Bhi = g_m2B_hi; Blo = g_m2B_lo;
        C = g_adjAe; K = NN; ncols = NE; oscale = DV_UNSCALE;
    }
    const bool twoterm = (which == 1);
    // triangular tile decode: t -> (bi >= bj)
    const int t = blockIdx.x;
    int bi = (int)((sqrtf(8.0f * (float)t + 1.0f) - 1.0f) * 0.5f);
    while ((bi + 1) * (bi + 2) / 2 <= t) bi++;
    while (bi * (bi + 1) / 2 > t) bi--;
    const int bj = t - bi * (bi + 1) / 2;
    const int m0 = bi * 128, n0 = bj * 128;
    const bool diagtile = (bi == bj);

    const u32 st0 = smem_u32(smem);
    const int tid = threadIdx.x;
    const int lane = tid & 31, wid = tid >> 5;
    const int wm = wid >> 1, wn = wid & 1;          // 2 x 2 warp grid, 64x64 tiles
    const int nk = K / KB;

    float acc[4][8][4];
#pragma unroll
    for (int i = 0; i < 4; i++)
#pragma unroll
        for (int j = 0; j < 8; j++)
#pragma unroll
            for (int q = 0; q < 4; q++) acc[i][j][q] = 0.f;

    stage_load(st0, 0, A, Bhi, Blo, K, m0, n0, 0, tid, twoterm);
    stage_load(st0, 1, A, Bhi, Blo, K, m0, n0, KB, tid, twoterm);

    const u32 arow = (u32)(wm * 64 + (lane & 15));
    const u32 brow = (u32)(wn * 64 + (lane & 15));
    const u32 asw = arow & 7, bsw = brow & 7;

    for (int kt = 0; kt < nk; kt++) {
        const int s = kt & 1;
        if (kt + 1 < nk) asm volatile("cp.async.wait_group 1;" ::: "memory");
        else             asm volatile("cp.async.wait_group 0;" ::: "memory");
        __syncthreads();

        const u32 base = st0 + s * STG_BYTES;
#pragma unroll
        for (int ks = 0; ks < 4; ks++) {
            const u32 cb = (u32)(ks * 2) + (u32)(lane >> 4);
            u32 Bh[8][2], Bl[8][2], Ah[4][4];
            const u32 boff = base + 16384 + brow * 128 + ((cb ^ bsw) << 4);
#pragma unroll
            for (int nip = 0; nip < 4; nip++) {
                u32 tr[4];
                LDSM4(tr, boff + nip * 2048);
                Bh[2 * nip][0] = tr[0]; Bh[2 * nip][1] = tr[2];
                Bh[2 * nip + 1][0] = tr[1]; Bh[2 * nip + 1][1] = tr[3];
            }
            if (twoterm) {
#pragma unroll
                for (int nip = 0; nip < 4; nip++) {
                    u32 tr[4];
                    LDSM4(tr, boff + 16384 + nip * 2048);
                    Bl[2 * nip][0] = tr[0]; Bl[2 * nip][1] = tr[2];
                    Bl[2 * nip + 1][0] = tr[1]; Bl[2 * nip + 1][1] = tr[3];
                }
            }
            const u32 aoff = base + arow * 128 + ((cb ^ asw) << 4);
#pragma unroll
            for (int mi = 0; mi < 4; mi++)
                LDSM4(Ah[mi], aoff + mi * 2048);
#pragma unroll
            for (int mi = 0; mi < 4; mi++)
#pragma unroll
                for (int ni = 0; ni < 8; ni++)
                    MMA_F16(acc[mi][ni], Ah[mi], Bh[ni]);
            if (twoterm) {
#pragma unroll
                for (int mi = 0; mi < 4; mi++)
#pragma unroll
                    for (int ni = 0; ni < 8; ni++)
                        MMA_F16(acc[mi][ni], Ah[mi], Bl[ni]);
            }
        }
        __syncthreads();
        if (kt + 2 < nk)
            stage_load(st0, s, A, Bhi, Blo, K, m0, n0, (kt + 2) * KB, tid, twoterm);
    }

    // ---------- epilogue ----------
    float* stg = (float*)smem;                         // 128 x TP floats (transpose staging)
    u32* scm = (u32*)(smem + 128 * TP * 4);            // 128 u32 colmax (direct block)
    if (which == 1 && tid < 128) scm[tid] = 0u;
    __syncthreads();

    u32 kmax[8][2];
#pragma unroll
    for (int ni = 0; ni < 8; ni++) { kmax[ni][0] = 0u; kmax[ni][1] = 0u; }

#pragma unroll
    for (int mi = 0; mi < 4; mi++) {
#pragma unroll
        for (int h = 0; h < 2; h++) {
            const int row_l = wm * 64 + mi * 16 + (lane >> 2) + h * 8;
            const int row_g = m0 + row_l;
            const size_t rb = (size_t)row_g * ncols;
#pragma unroll
            for (int ni = 0; ni < 8; ni++) {
                const int col_l = wn * 64 + ni * 8 + (lane & 3) * 2;
                const int col_g = n0 + col_l;
                float v0 = acc[mi][ni][h * 2] * oscale;
                float v1 = acc[mi][ni][h * 2 + 1] * oscale;
                if (diagtile) {
                    if (row_g == col_g) v0 = 1.0f;
                    if (row_g == col_g + 1) v1 = 1.0f;
                } else {
                    stg[row_l * TP + col_l] = v0;
                    stg[row_l * TP + col_l + 1] = v1;
                }
                const float2 a = *(const float2*)(adj + rb + col_g);
                float w0 = v0 * a.x, w1 = v1 * a.y;
                *(float2*)(C + rb + col_g) = make_float2(w0, w1);
                if (which == 1) {
                    kmax[ni][0] = max(kmax[ni][0], fkey(w0));
                    kmax[ni][1] = max(kmax[ni][1], fkey(w1));
                }
            }
        }
    }
    if (which == 1) {
#pragma unroll
        for (int ni = 0; ni < 8; ni++) {
            const int cl = wn * 64 + ni * 8 + (lane & 3) * 2;
            atomicMax(scm + cl, kmax[ni][0]);
            atomicMax(scm + cl + 1, kmax[ni][1]);
        }
    }
    __syncthreads();
    if (which == 1 && tid < 128) atomicMax(g_cmaxu + n0 + tid, scm[tid]);

    // mirror block: C[n0+c][m0+r] = M[r][c] * adj[n0+c][m0+r]
    if (!diagtile) {
        u32 kloc[4] = {0u, 0u, 0u, 0u};
        for (int cc = 0; cc < 32; cc++) {
            const int c = wid * 32 + cc;
            const size_t orow = (size_t)(n0 + c) * ncols + m0;
#pragma unroll
            for (int ch = 0; ch < 4; ch++) {
                const int r = ch * 32 + lane;
                float v = stg[r * TP + c];
                float w = v * adj[orow + r];
                C[orow + r] = w;
                if (which == 1) kloc[ch] = max(kloc[ch], fkey(w));
            }
        }
        if (which == 1) {
#pragma unroll
            for (int ch = 0; ch < 4; ch++)
                atomicMax(g_cmaxu + m0 + ch * 32 + lane, kloc[ch]);
        }
    }
}

// =====================  Hv partials: g_hvp[kc] = adjAv[:, kc*512:(kc+1)*512] @ HW  ======
__global__ __launch_bounds__(256) void k_hv(float* __restrict__ dummy) {
    __shared__ __align__(16) float As[32 * 32];
    __shared__ __align__(16) float Bs[32 * 64];
    const int tid = threadIdx.x;
    const int tx = tid & 15, ty = tid >> 4;
    const int m0 = blockIdx.x * 32;
    const int kc = blockIdx.y;
    const int arow = tid >> 3, ac4 = (tid & 7) * 4;
    const int brow = tid >> 4, bc4 = (tid & 15) * 4;
    float acc[2][4] = {{0, 0, 0, 0}, {0, 0, 0, 0}};
    for (int k0 = kc * 512; k0 < (kc + 1) * 512; k0 += 32) {
        float4 fa = *(const float4*)(g_adjAv + (m0 + arow) * NN + k0 + ac4);
        float4 fb0 = *(const float4*)(g_HW + (k0 + brow) * DVO + bc4);
        float4 fb1 = *(const float4*)(g_HW + (k0 + brow + 16) * DVO + bc4);
        __syncthreads();
        As[(ac4 + 0) * 32 + arow] = fa.x; As[(ac4 + 1) * 32 + arow] = fa.y;
        As[(ac4 + 2) * 32 + arow] = fa.z; As[(ac4 + 3) * 32 + arow] = fa.w;
        *(float4*)(Bs + brow * 64 + bc4) = fb0;
        *(float4*)(Bs + (brow + 16) * 64 + bc4) = fb1;
        __syncthreads();
#pragma unroll
        for (int kk = 0; kk < 32; kk++) {
            float a0 = As[kk * 32 + ty * 2];
            float a1 = As[kk * 32 + ty * 2 + 1];
            float4 b = *(const float4*)(Bs + kk * 64 + tx * 4);
            acc[0][0] += a0 * b.x; acc[0][1] += a0 * b.y; acc[0][2] += a0 * b.z; acc[0][3] += a0 * b.w;
            acc[1][0] += a1 * b.x; acc[1][1] += a1 * b.y; acc[1][2] += a1 * b.z; acc[1][3] += a1 * b.w;
        }
    }
#pragma unroll
    for (int r = 0; r < 2; r++) {
        int row = m0 + ty * 2 + r;
        *(float4*)(g_hvp[kc] + row * DVO + tx * 4) =
            make_float4(acc[r][0], acc[r][1], acc[r][2], acc[r][3]);
    }
}

// reduce partials + bias -> out
__global__ void k_hvred(const float* __restrict__ bv, float* __restrict__ out) {
    int idx = blockIdx.x * 256 + threadIdx.x;          // 131072
    int c = idx & 63;
    float s = bv[c] + g_hvp[0][idx] + g_hvp[1][idx] + g_hvp[2][idx] + g_hvp[3][idx];
    out[idx] = s;
}

__global__ void k_dv(const float* __restrict__ Hv, const float* __restrict__ pe) {
    int w = (blockIdx.x * blockDim.x + threadIdx.x) >> 5;
    int lane = threadIdx.x & 31;
    float s = Hv[w * DVO + lane] * pe[lane] + Hv[w * DVO + 32 + lane] * pe[32 + lane];
#pragma unroll
    for (int o = 16; o > 0; o >>= 1) s += __shfl_down_sync(0xffffffffu, s, o);
    if (lane == 0) g_dv[w] = s;
}

// finalize colmax from keys, fold 1/(max+1e-10) into HeW -> HeWs
__global__ void k_cmax2() {
    int col = blockIdx.x * 256 + threadIdx.x;
    u32 k = g_cmaxu[col];
    u32 b = (k & 0x80000000u) ? (k ^ 0x80000000u) : ~k;
    float m = __uint_as_float(b);
    float inv = 1.0f / (m + 1e-10f);
#pragma unroll
    for (int c = 0; c < DEO; c++) g_HeWs[col * DEO + c] = g_HeW[col * DEO + c] * inv;
}

__global__ __launch_bounds__(256) void k_he(const float* __restrict__ be, float* __restrict__ out) {
    __shared__ __align__(16) float As[64 * 64];
    __shared__ __align__(16) float Bs[64 * 16];
    const int tid = threadIdx.x;
    const int c = tid & 15, tr = tid >> 4;
    const int m0 = blockIdx.x * 64;
    const int lc4 = (tid & 15) * 4;
    float acc[4] = {0, 0, 0, 0};
    for (int k0 = 0; k0 < NE; k0 += 64) {
        float4 ra[4]; float rb[4];
#pragma unroll
        for (int q = 0; q < 4; q++) {
            int row = tr + q * 16;
            ra[q] = *(const float4*)(g_adjAe + (size_t)(m0 + row) * NE + k0 + lc4);
            rb[q] = g_HeWs[(k0 + row) * DEO + c];
        }
        __syncthreads();
#pragma unroll
        for (int q = 0; q < 4; q++) {
            int row = tr + q * 16;
            *(float4*)(As + row * 64 + lc4) = ra[q];
            Bs[row * 16 + c] = rb[q];
        }
        __syncthreads();
#pragma unroll 8
        for (int kk = 0; kk < 64; kk++) {
            float b = Bs[kk * 16 + c];
            acc[0] += As[(0 * 16 + tr) * 64 + kk] * b;
            acc[1] += As[(1 * 16 + tr) * 64 + kk] * b;
            acc[2] += As[(2 * 16 + tr) * 64 + kk] * b;
            acc[3] += As[(3 * 16 + tr) * 64 + kk] * b;
        }
    }
    float bc = be[c];
#pragma unroll
    for (int q = 0; q < 4; q++)
        out[(m0 + q * 16 + tr) * DEO + c] = acc[q] + bc;
}

// =====================  launch  =====================
extern "C" void kernel_launch(void* const* d_in, const int* in_sizes, int n_in,
                              void* d_out, int out_size) {
    const float* H_v  = (const float*)d_in[0];
    const float* H_e  = (const float*)d_in[1];
    const float* adjv = (const float*)d_in[2];
    const float* adje = (const float*)d_in[3];
    const float* T    = (const float*)d_in[4];
    const float* W_v  = (const float*)d_in[5];
    const float* b_v  = (const float*)d_in[6];
    const float* p_v  = (const float*)d_in[7];
    const float* W_e  = (const float*)d_in[8];
    const float* b_e  = (const float*)d_in[9];
    const float* p_e  = (const float*)d_in[10];
    float* out = (float*)d_out;
    (void)in_sizes; (void)n_in; (void)out_size;

    cudaFuncSetAttribute(k_mult_mma, cudaFuncAttributeMaxDynamicSharedMemorySize, SMEM_DYN);

    k_de<<<24, 256>>>(H_e, p_v);
    k_hew<<<384, 256>>>(H_e, W_e);
    k_hw<<<512, 256>>>(H_v, W_v);
    k_cinit<<<24, 256>>>();
    k_split1<<<12288, 256>>>(T);
    k_mult_mma<<<136, 128, SMEM_DYN>>>(0, adjv);    // adjAv, fp16 1-term, triangular
    k_hv<<<dim3(64, 4), 256>>>(out);                // split-K partials
    k_hvred<<<512, 256>>>(b_v, out);                // reduce + bias -> Hv_out
    k_dv<<<256, 256>>>(out, p_e);
    k_split2<<<dim3(192, 32), dim3(32, 8)>>>(T);
    k_mult_mma<<<1176, 128, SMEM_DYN>>>(1, adje);   // adjAe, fp16 2-term, triangular
    k_cmax2<<<24, 256>>>();
    k_he<<<96, 256>>>(b_e, out + NN * DVO);
}

// round 13
// speedup vs baseline: 3.6019x; 1.3680x over previous
#include <cuda_runtime.h>
#include <cuda_fp16.h>
#include <cstdint>

typedef unsigned int u32;
typedef unsigned long long u64;

#define NN 2048
#define NE 6144
#define KDV 128
#define DVO 64
#define DEI 16
#define DEO 16

#define DV_SCALE (1.0f / 256.0f)
#define DV_UNSCALE 256.0f

// =====================  scratch  =====================
__device__ __align__(16) __half g_m1A[NN * NE];         // fp16(T * d_e[col])
__device__ __align__(16) __half g_m1B[NN * NE];         // fp16(T)
__device__ __align__(16) __half g_m2A[NE * NN];         // fp16(T^T * d_v * 2^-8)
__device__ __align__(16) __half g_m2B[NE * NN];         // fp16(T^T)
__device__ __align__(16) float g_adjAv[NN * NN];
__device__ __align__(16) float g_adjAe[(size_t)NE * NE];
__device__ __align__(16) float g_HW[NN * DVO];
__device__ __align__(16) float g_hvp[4][NN * DVO];      // k_hv split-K partials
__device__ __align__(16) float g_HeW[NE * DEO];
__device__ __align__(16) float g_HeWs[NE * DEO];
__device__ __align__(16) float g_de[NE];
__device__ __align__(16) float g_dv[NN];
__device__ u32 g_cmaxu[NE];

// =====================  helpers  =====================
__device__ __forceinline__ u32 smem_u32(const void* p) {
    u32 a;
    asm("{ .reg .u64 t; cvta.to.shared.u64 t, %1; cvt.u32.u64 %0, t; }" : "=r"(a) : "l"(p));
    return a;
}

__device__ __forceinline__ void cp16(u32 saddr, const __half* gptr) {
    asm volatile("cp.async.cg.shared.global [%0], [%1], 16;"
                 :: "r"(saddr), "l"(__cvta_generic_to_global(gptr)) : "memory");
}

#define LDSM4(r, addr)                                                          \
    asm volatile("ldmatrix.sync.aligned.m8n8.x4.shared.b16 {%0,%1,%2,%3}, [%4];" \
                 : "=r"((r)[0]), "=r"((r)[1]), "=r"((r)[2]), "=r"((r)[3]) : "r"(addr))

#define MMA_F16(d, a, b)                                                         \
    asm volatile("mma.sync.aligned.m16n8k16.row.col.f32.f16.f16.f32 "            \
                 "{%0,%1,%2,%3},{%4,%5,%6,%7},{%8,%9},{%0,%1,%2,%3};"            \
                 : "+f"((d)[0]), "+f"((d)[1]), "+f"((d)[2]), "+f"((d)[3])        \
                 : "r"((a)[0]), "r"((a)[1]), "r"((a)[2]), "r"((a)[3]),           \
                   "r"((b)[0]), "r"((b)[1]))

__device__ __forceinline__ u32 pkh2(__half a, __half b) {
    __half2 h = __halves2half2(a, b);
    return *(u32*)&h;
}
__device__ __forceinline__ u32 fkey(float f) {
    u32 b = __float_as_uint(f);
    return (b & 0x80000000u) ? ~b : (b | 0x80000000u);
}

// =====================  tiny prologue kernels  =====================
__global__ void k_de(const float* __restrict__ He, const float* __restrict__ pv) {
    int e = blockIdx.x * 256 + threadIdx.x;
    float s = 0.f;
#pragma unroll
    for (int k = 0; k < DEI; k++) s += He[e * DEI + k] * pv[k];
    g_de[e] = s;
}

__global__ void k_hew(const float* __restrict__ He, const float* __restrict__ We) {
    int idx = blockIdx.x * 256 + threadIdx.x;
    int e = idx >> 4, c = idx & 15;
    float s = 0.f;
#pragma unroll
    for (int k = 0; k < DEI; k++) s += He[e * DEI + k] * We[k * DEO + c];
    g_HeW[idx] = s;
}

__global__ void k_hw(const float* __restrict__ Hv, const float* __restrict__ Wv) {
    int idx = blockIdx.x * 256 + threadIdx.x;
    int i = idx >> 6, c = idx & 63;
    float s = 0.f;
#pragma unroll 8
    for (int k = 0; k < KDV; k++) s += Hv[i * KDV + k] * Wv[k * DVO + c];
    g_HW[idx] = s;
}

__global__ void k_cinit() {
    g_cmaxu[blockIdx.x * 256 + threadIdx.x] = 0u;
}

// mult1 prep: B = fp16(T), A = fp16(T * d_e[col]). [NN][NE] K-major.
__global__ void k_split1(const float* __restrict__ T) {
    size_t i = (size_t)blockIdx.x * 256 + threadIdx.x;   // float4 index
    float4 t = ((const float4*)T)[i];
    int col = (int)((i * 4) % NE);
    float4 de = *(const float4*)(g_de + col);
    ((uint2*)g_m1B)[i] = make_uint2(
        pkh2(__float2half_rn(t.x), __float2half_rn(t.y)),
        pkh2(__float2half_rn(t.z), __float2half_rn(t.w)));
    ((uint2*)g_m1A)[i] = make_uint2(
        pkh2(__float2half_rn(t.x * de.x), __float2half_rn(t.y * de.y)),
        pkh2(__float2half_rn(t.z * de.z), __float2half_rn(t.w * de.w)));
}

// mult2 prep (transpose): B2[m][k] = fp16(T[k][m]); A2[m][k] = fp16(T[k][m]*d_v[k]*2^-8).
__global__ void k_split2(const float* __restrict__ T) {
    __shared__ float tile[64][33];
    const int m0 = blockIdx.x * 32, k0 = blockIdx.y * 64;
    const int tx = threadIdx.x, ty = threadIdx.y;     // (32, 8)
#pragma unroll
    for (int j = 0; j < 8; j++) {
        int r = ty + j * 8;
        tile[r][tx] = T[(size_t)(k0 + r) * NE + m0 + tx];
    }
    __syncthreads();
    const int lane = tx, w = ty;
    float2 dv = ((const float2*)(g_dv + k0))[lane];
    dv.x *= DV_SCALE; dv.y *= DV_SCALE;
#pragma unroll
    for (int q = 0; q < 4; q++) {
        const int mloc = w + 8 * q;
        const int m = m0 + mloc;
        float v0 = tile[2 * lane][mloc];
        float v1 = tile[2 * lane + 1][mloc];
        const size_t ob = ((size_t)m * NN + k0) >> 1;   // u32 index
        ((u32*)g_m2B)[ob + lane] = pkh2(__float2half_rn(v0), __float2half_rn(v1));
        ((u32*)g_m2A)[ob + lane] =
            pkh2(__float2half_rn(v0 * dv.x), __float2half_rn(v1 * dv.y));
    }
}

// =====================  fp16 1-term tensor-core GEMM, SYMMETRIC (triangular tiles)  ========
// M = A*B; which==0: oscale=1 (adjAv); which==1: oscale=256 (adjAe, undo dv scale) + colmax
#define KB 64
#define STG_BYTES 32768          // A 16K | B 16K
#define TP 129                   // transpose pitch (floats)
#define SMEM_DYN (128 * TP * 4 + 512)   // 66560 > 2*STG_BYTES = 65536

__device__ __forceinline__ void stage_load(u32 st0, int s,
        const __half* __restrict__ A, const __half* __restrict__ B,
        int K, int m0, int n0, int k0, int tid) {
    u32 base = st0 + s * STG_BYTES;
#pragma unroll
    for (int i = 0; i < 8; i++) {
        int id = tid + i * 128;                // 0..1023
        int r = id >> 3, c = id & 7;           // 128 rows x 8 16B-chunks
        u32 so = (u32)(r * 128 + ((c ^ (r & 7)) << 4));
        cp16(base + so, A + (size_t)(m0 + r) * K + k0 + c * 8);
        cp16(base + 16384 + so, B + (size_t)(n0 + r) * K + k0 + c * 8);
    }
    asm volatile("cp.async.commit_group;" ::: "memory");
}

__global__ __launch_bounds__(128, 2) void k_mult_mma(int which, const float* __restrict__ adj) {
    extern __shared__ char smem[];
    const __half *A, *B;
    float* C;
    int K, ncols;
    float oscale;
    if (which == 0) {
        A = g_m1A; B = g_m1B;
        C = g_adjAv; K = NE; ncols = NN; oscale = 1.0f;
    } else {
        A = g_m2A; B = g_m2B;
        C = g_adjAe; K = NN; ncols = NE; oscale = DV_UNSCALE;
    }
    // triangular tile decode: t -> (bi >= bj)
    const int t = blockIdx.x;
    int bi = (int)((sqrtf(8.0f * (float)t + 1.0f) - 1.0f) * 0.5f);
    while ((bi + 1) * (bi + 2) / 2 <= t) bi++;
    while (bi * (bi + 1) / 2 > t) bi--;
    const int bj = t - bi * (bi + 1) / 2;
    const int m0 = bi * 128, n0 = bj * 128;
    const bool diagtile = (bi == bj);

    const u32 st0 = smem_u32(smem);
    const int tid = threadIdx.x;
    const int lane = tid & 31, wid = tid >> 5;
    const int wm = wid >> 1, wn = wid & 1;          // 2 x 2 warp grid, 64x64 tiles
    const int nk = K / KB;

    float acc[4][8][4];
#pragma unroll
    for (int i = 0; i < 4; i++)
#pragma unroll
        for (int j = 0; j < 8; j++)
#pragma unroll
            for (int q = 0; q < 4; q++) acc[i][j][q] = 0.f;

    stage_load(st0, 0, A, B, K, m0, n0, 0, tid);
    stage_load(st0, 1, A, B, K, m0, n0, KB, tid);

    const u32 arow = (u32)(wm * 64 + (lane & 15));
    const u32 brow = (u32)(wn * 64 + (lane & 15));
    const u32 asw = arow & 7, bsw = brow & 7;

    for (int kt = 0; kt < nk; kt++) {
        const int s = kt & 1;
        if (kt + 1 < nk) asm volatile("cp.async.wait_group 1;" ::: "memory");
        else             asm volatile("cp.async.wait_group 0;" ::: "memory");
        __syncthreads();

        const u32 base = st0 + s * STG_BYTES;
#pragma unroll
        for (int ks = 0; ks < 4; ks++) {
            const u32 cb = (u32)(ks * 2) + (u32)(lane >> 4);
            u32 Bh[8][2], Ah[4][4];
            const u32 boff = base + 16384 + brow * 128 + ((cb ^ bsw) << 4);
#pragma unroll
            for (int nip = 0; nip < 4; nip++) {
                u32 tr[4];
                LDSM4(tr, boff + nip * 2048);
                Bh[2 * nip][0] = tr[0]; Bh[2 * nip][1] = tr[2];
                Bh[2 * nip + 1][0] = tr[1]; Bh[2 * nip + 1][1] = tr[3];
            }
            const u32 aoff = base + arow * 128 + ((cb ^ asw) << 4);
#pragma unroll
            for (int mi = 0; mi < 4; mi++)
                LDSM4(Ah[mi], aoff + mi * 2048);
#pragma unroll
            for (int mi = 0; mi < 4; mi++)
#pragma unroll
                for (int ni = 0; ni < 8; ni++)
                    MMA_F16(acc[mi][ni], Ah[mi], Bh[ni]);
        }
        __syncthreads();
        if (kt + 2 < nk)
            stage_load(st0, s, A, B, K, m0, n0, (kt + 2) * KB, tid);
    }

    // ---------- epilogue ----------
    float* stg = (float*)smem;                         // 128 x TP floats (transpose staging)
    u32* scm = (u32*)(smem + 128 * TP * 4);            // 128 u32 colmax (direct block)
    if (which == 1 && tid < 128) scm[tid] = 0u;
    __syncthreads();

    u32 kmax[8][2];
#pragma unroll
    for (int ni = 0; ni < 8; ni++) { kmax[ni][0] = 0u; kmax[ni][1] = 0u; }

#pragma unroll
    for (int mi = 0; mi < 4; mi++) {
#pragma unroll
        for (int h = 0; h < 2; h++) {
            const int row_l = wm * 64 + mi * 16 + (lane >> 2) + h * 8;
            const int row_g = m0 + row_l;
            const size_t rb = (size_t)row_g * ncols;
#pragma unroll
            for (int ni = 0; ni < 8; ni++) {
                const int col_l = wn * 64 + ni * 8 + (lane & 3) * 2;
                const int col_g = n0 + col_l;
                float v0 = acc[mi][ni][h * 2] * oscale;
                float v1 = acc[mi][ni][h * 2 + 1] * oscale;
                if (diagtile) {
                    if (row_g == col_g) v0 = 1.0f;
                    if (row_g == col_g + 1) v1 = 1.0f;
                } else {
                    stg[row_l * TP + col_l] = v0;
                    stg[row_l * TP + col_l + 1] = v1;
                }
                const float2 a = *(const float2*)(adj + rb + col_g);
                float w0 = v0 * a.x, w1 = v1 * a.y;
                *(float2*)(C + rb + col_g) = make_float2(w0, w1);
                if (which == 1) {
                    kmax[ni][0] = max(kmax[ni][0], fkey(w0));
                    kmax[ni][1] = max(kmax[ni][1], fkey(w1));
                }
            }
        }
    }
    if (which == 1) {
#pragma unroll
        for (int ni = 0; ni < 8; ni++) {
            const int cl = wn * 64 + ni * 8 + (lane & 3) * 2;
            atomicMax(scm + cl, kmax[ni][0]);
            atomicMax(scm + cl + 1, kmax[ni][1]);
        }
    }
    __syncthreads();
    if (which == 1 && tid < 128) atomicMax(g_cmaxu + n0 + tid, scm[tid]);

    // mirror block: C[n0+c][m0+r] = M[r][c] * adj[n0+c][m0+r]
    if (!diagtile) {
        u32 kloc[4] = {0u, 0u, 0u, 0u};
        for (int cc = 0; cc < 32; cc++) {
            const int c = wid * 32 + cc;
            const size_t orow = (size_t)(n0 + c) * ncols + m0;
#pragma unroll
            for (int ch = 0; ch < 4; ch++) {
                const int r = ch * 32 + lane;
                float v = stg[r * TP + c];
                float w = v * adj[orow + r];
                C[orow + r] = w;
                if (which == 1) kloc[ch] = max(kloc[ch], fkey(w));
            }
        }
        if (which == 1) {
#pragma unroll
            for (int ch = 0; ch < 4; ch++)
                atomicMax(g_cmaxu + m0 + ch * 32 + lane, kloc[ch]);
        }
    }
}

// =====================  Hv partials: g_hvp[kc] = adjAv[:, kc*512:(kc+1)*512] @ HW  ======
__global__ __launch_bounds__(256) void k_hv(float* __restrict__ dummy) {
    __shared__ __align__(16) float As[32 * 32];
    __shared__ __align__(16) float Bs[32 * 64];
    const int tid = threadIdx.x;
    const int tx = tid & 15, ty = tid >> 4;
    const int m0 = blockIdx.x * 32;
    const int kc = blockIdx.y;
    const int arow = tid >> 3, ac4 = (tid & 7) * 4;
    const int brow = tid >> 4, bc4 = (tid & 15) * 4;
    float acc[2][4] = {{0, 0, 0, 0}, {0, 0, 0, 0}};
    for (int k0 = kc * 512; k0 < (kc + 1) * 512; k0 += 32) {
        float4 fa = *(const float4*)(g_adjAv + (m0 + arow) * NN + k0 + ac4);
        float4 fb0 = *(const float4*)(g_HW + (k0 + brow) * DVO + bc4);
        float4 fb1 = *(const float4*)(g_HW + (k0 + brow + 16) * DVO + bc4);
        __syncthreads();
        As[(ac4 + 0) * 32 + arow] = fa.x; As[(ac4 + 1) * 32 + arow] = fa.y;
        As[(ac4 + 2) * 32 + arow] = fa.z; As[(ac4 + 3) * 32 + arow] = fa.w;
        *(float4*)(Bs + brow * 64 + bc4) = fb0;
        *(float4*)(Bs + (brow + 16) * 64 + bc4) = fb1;
        __syncthreads();
#pragma unroll
        for (int kk = 0; kk < 32; kk++) {
            float a0 = As[kk * 32 + ty * 2];
            float a1 = As[kk * 32 + ty * 2 + 1];
            float4 b = *(const float4*)(Bs + kk * 64 + tx * 4);
            acc[0][0] += a0 * b.x; acc[0][1] += a0 * b.y; acc[0][2] += a0 * b.z; acc[0][3] += a0 * b.w;
            acc[1][0] += a1 * b.x; acc[1][1] += a1 * b.y; acc[1][2] += a1 * b.z; acc[1][3] += a1 * b.w;
        }
    }
#pragma unroll
    for (int r = 0; r < 2; r++) {
        int row = m0 + ty * 2 + r;
        *(float4*)(g_hvp[kc] + row * DVO + tx * 4) =
            make_float4(acc[r][0], acc[r][1], acc[r][2], acc[r][3]);
    }
}

// reduce partials + bias -> out
__global__ void k_hvred(const float* __restrict__ bv, float* __restrict__ out) {
    int idx = blockIdx.x * 256 + threadIdx.x;          // 131072
    int c = idx & 63;
    float s = bv[c] + g_hvp[0][idx] + g_hvp[1][idx] + g_hvp[2][idx] + g_hvp[3][idx];
    out[idx] = s;
}

__global__ void k_dv(const float* __restrict__ Hv, const float* __restrict__ pe) {
    int w = (blockIdx.x * blockDim.x + threadIdx.x) >> 5;
    int lane = threadIdx.x & 31;
    float s = Hv[w * DVO + lane] * pe[lane] + Hv[w * DVO + 32 + lane] * pe[32 + lane];
#pragma unroll
    for (int o = 16; o > 0; o >>= 1) s += __shfl_down_sync(0xffffffffu, s, o);
    if (lane == 0) g_dv[w] = s;
}

// finalize colmax from keys, fold 1/(max+1e-10) into HeW -> HeWs
__global__ void k_cmax2() {
    int col = blockIdx.x * 256 + threadIdx.x;
    u32 k = g_cmaxu[col];
    u32 b = (k & 0x80000000u) ? (k ^ 0x80000000u) : ~k;
    float m = __uint_as_float(b);
    float inv = 1.0f / (m + 1e-10f);
#pragma unroll
    for (int c = 0; c < DEO; c++) g_HeWs[col * DEO + c] = g_HeW[col * DEO + c] * inv;
}

__global__ __launch_bounds__(256) void k_he(const float* __restrict__ be, float* __restrict__ out) {
    __shared__ __align__(16) float As[64 * 64];
    __shared__ __align__(16) float Bs[64 * 16];
    const int tid = threadIdx.x;
    const int c = tid & 15, tr = tid >> 4;
    const int m0 = blockIdx.x * 64;
    const int lc4 = (tid & 15) * 4;
    float acc[4] = {0, 0, 0, 0};
    for (int k0 = 0; k0 < NE; k0 += 64) {
        float4 ra[4]; float rb[4];
#pragma unroll
        for (int q = 0; q < 4; q++) {
            int row = tr + q * 16;
            ra[q] = *(const float4*)(g_adjAe + (size_t)(m0 + row) * NE + k0 + lc4);
            rb[q] = g_HeWs[(k0 + row) * DEO + c];
        }
        __syncthreads();
#pragma unroll
        for (int q = 0; q < 4; q++) {
            int row = tr + q * 16;
            *(float4*)(As + row * 64 + lc4) = ra[q];
            Bs[row * 16 + c] = rb[q];
        }
        __syncthreads();
#pragma unroll 8
        for (int kk = 0; kk < 64; kk++) {
            float b = Bs[kk * 16 + c];
            acc[0] += As[(0 * 16 + tr) * 64 + kk] * b;
            acc[1] += As[(1 * 16 + tr) * 64 + kk] * b;
            acc[2] += As[(2 * 16 + tr) * 64 + kk] * b;
            acc[3] += As[(3 * 16 + tr) * 64 + kk] * b;
        }
    }
    float bc = be[c];
#pragma unroll
    for (int q = 0; q < 4; q++)
        out[(m0 + q * 16 + tr) * DEO + c] = acc[q] + bc;
}

// =====================  launch  =====================
extern "C" void kernel_launch(void* const* d_in, const int* in_sizes, int n_in,
                              void* d_out, int out_size) {
    const float* H_v  = (const float*)d_in[0];
    const float* H_e  = (const float*)d_in[1];
    const float* adjv = (const float*)d_in[2];
    const float* adje = (const float*)d_in[3];
    const float* T    = (const float*)d_in[4];
    const float* W_v  = (const float*)d_in[5];
    const float* b_v  = (const float*)d_in[6];
    const float* p_v  = (const float*)d_in[7];
    const float* W_e  = (const float*)d_in[8];
    const float* b_e  = (const float*)d_in[9];
    const float* p_e  = (const float*)d_in[10];
    float* out = (float*)d_out;
    (void)in_sizes; (void)n_in; (void)out_size;

    cudaFuncSetAttribute(k_mult_mma, cudaFuncAttributeMaxDynamicSharedMemorySize, SMEM_DYN);

    k_de<<<24, 256>>>(H_e, p_v);
    k_hew<<<384, 256>>>(H_e, W_e);
    k_hw<<<512, 256>>>(H_v, W_v);
    k_cinit<<<24, 256>>>();
    k_split1<<<12288, 256>>>(T);
    k_mult_mma<<<136, 128, SMEM_DYN>>>(0, adjv);    // adjAv, fp16 1-term, triangular
    k_hv<<<dim3(64, 4), 256>>>(out);                // split-K partials
    k_hvred<<<512, 256>>>(b_v, out);                // reduce + bias -> Hv_out
    k_dv<<<256, 256>>>(out, p_e);
    k_split2<<<dim3(192, 32), dim3(32, 8)>>>(T);
    k_mult_mma<<<1176, 128, SMEM_DYN>>>(1, adje);   // adjAe, fp16 1-term, triangular + colmax
    k_cmax2<<<24, 256>>>();
    k_he<<<96, 256>>>(b_e, out + NN * DVO);
}

// round 14
// speedup vs baseline: 4.7233x; 1.3113x over previous
#include <cuda_runtime.h>
#include <cuda_fp16.h>
#include <cstdint>

typedef unsigned int u32;
typedef unsigned long long u64;

#define NN 2048
#define NE 6144
#define KDV 128
#define DVO 64
#define DEI 16
#define DEO 16

#define DV_SCALE (1.0f / 1024.0f)   // mult2 scale (fp16 range headroom)
#define HE_SCALE 4096.0f            // HeWsT pre-scale
#define HE_UNSCALE (1.0f / 4096.0f)

// =====================  scratch  =====================
__device__ __align__(16) __half g_m1A[NN * NE];         // fp16(T * d_e[col])
__device__ __align__(16) __half g_m1B[NN * NE];         // fp16(T)
__device__ __align__(16) __half g_m2A[NE * NN];         // fp16(T^T * d_v * 2^-10)
__device__ __align__(16) __half g_m2B[NE * NN];         // fp16(T^T)
__device__ __align__(16) float g_adjAv[NN * NN];
__device__ __align__(16) __half g_adjAe[(size_t)NE * NE];   // fp16, scaled by 2^-10
__device__ __align__(16) float g_HW[NN * DVO];
__device__ __align__(16) float g_hvp[4][NN * DVO];      // k_hv split-K partials
__device__ __align__(16) float g_HeW[NE * DEO];
__device__ __align__(16) __half g_HeWsT[DEO * NE];      // fp16 (HeW/colmax_s)^T * 2^12
__device__ __align__(16) float g_hep[4][NE * DEO];      // k_he split-K partials
__device__ __align__(16) float g_de[NE];
__device__ __align__(16) float g_dv[NN];
__device__ u32 g_cmaxu[NE];

// =====================  helpers  =====================
__device__ __forceinline__ u32 smem_u32(const void* p) {
    u32 a;
    asm("{ .reg .u64 t; cvta.to.shared.u64 t, %1; cvt.u32.u64 %0, t; }" : "=r"(a) : "l"(p));
    return a;
}

__device__ __forceinline__ void cp16(u32 saddr, const __half* gptr) {
    asm volatile("cp.async.cg.shared.global [%0], [%1], 16;"
                 :: "r"(saddr), "l"(__cvta_generic_to_global(gptr)) : "memory");
}

#define LDSM4(r, addr)                                                          \
    asm volatile("ldmatrix.sync.aligned.m8n8.x4.shared.b16 {%0,%1,%2,%3}, [%4];" \
                 : "=r"((r)[0]), "=r"((r)[1]), "=r"((r)[2]), "=r"((r)[3]) : "r"(addr))

#define MMA_F16(d, a, b)                                                         \
    asm volatile("mma.sync.aligned.m16n8k16.row.col.f32.f16.f16.f32 "            \
                 "{%0,%1,%2,%3},{%4,%5,%6,%7},{%8,%9},{%0,%1,%2,%3};"            \
                 : "+f"((d)[0]), "+f"((d)[1]), "+f"((d)[2]), "+f"((d)[3])        \
                 : "r"((a)[0]), "r"((a)[1]), "r"((a)[2]), "r"((a)[3]),           \
                   "r"((b)[0]), "r"((b)[1]))

__device__ __forceinline__ u32 pkh2(__half a, __half b) {
    __half2 h = __halves2half2(a, b);
    return *(u32*)&h;
}
__device__ __forceinline__ u32 fkey(float f) {
    u32 b = __float_as_uint(f);
    return (b & 0x80000000u) ? ~b : (b | 0x80000000u);
}

// =====================  tiny prologue kernels  =====================
__global__ void k_de(const float* __restrict__ He, const float* __restrict__ pv) {
    int e = blockIdx.x * 256 + threadIdx.x;
    float s = 0.f;
#pragma unroll
    for (int k = 0; k < DEI; k++) s += He[e * DEI + k] * pv[k];
    g_de[e] = s;
    g_cmaxu[e] = 0u;            // fused colmax init
}

__global__ void k_hew(const float* __restrict__ He, const float* __restrict__ We) {
    int idx = blockIdx.x * 256 + threadIdx.x;
    int e = idx >> 4, c = idx & 15;
    float s = 0.f;
#pragma unroll
    for (int k = 0; k < DEI; k++) s += He[e * DEI + k] * We[k * DEO + c];
    g_HeW[idx] = s;
}

__global__ void k_hw(const float* __restrict__ Hv, const float* __restrict__ Wv) {
    int idx = blockIdx.x * 256 + threadIdx.x;
    int i = idx >> 6, c = idx & 63;
    float s = 0.f;
#pragma unroll 8
    for (int k = 0; k < KDV; k++) s += Hv[i * KDV + k] * Wv[k * DVO + c];
    g_HW[idx] = s;
}

// mult1 prep: B = fp16(T), A = fp16(T * d_e[col]). [NN][NE] K-major.
__global__ void k_split1(const float* __restrict__ T) {
    size_t i = (size_t)blockIdx.x * 256 + threadIdx.x;   // float4 index
    float4 t = ((const float4*)T)[i];
    int col = (int)((i * 4) % NE);
    float4 de = *(const float4*)(g_de + col);
    ((uint2*)g_m1B)[i] = make_uint2(
        pkh2(__float2half_rn(t.x), __float2half_rn(t.y)),
        pkh2(__float2half_rn(t.z), __float2half_rn(t.w)));
    ((uint2*)g_m1A)[i] = make_uint2(
        pkh2(__float2half_rn(t.x * de.x), __float2half_rn(t.y * de.y)),
        pkh2(__float2half_rn(t.z * de.z), __float2half_rn(t.w * de.w)));
}

// mult2 prep (transpose): B2[m][k] = fp16(T[k][m]); A2[m][k] = fp16(T[k][m]*d_v[k]*2^-10).
__global__ void k_split2(const float* __restrict__ T) {
    __shared__ float tile[64][33];
    const int m0 = blockIdx.x * 32, k0 = blockIdx.y * 64;
    const int tx = threadIdx.x, ty = threadIdx.y;     // (32, 8)
#pragma unroll
    for (int j = 0; j < 8; j++) {
        int r = ty + j * 8;
        tile[r][tx] = T[(size_t)(k0 + r) * NE + m0 + tx];
    }
    __syncthreads();
    const int lane = tx, w = ty;
    float2 dv = ((const float2*)(g_dv + k0))[lane];
    dv.x *= DV_SCALE; dv.y *= DV_SCALE;
#pragma unroll
    for (int q = 0; q < 4; q++) {
        const int mloc = w + 8 * q;
        const int m = m0 + mloc;
        float v0 = tile[2 * lane][mloc];
        float v1 = tile[2 * lane + 1][mloc];
        const size_t ob = ((size_t)m * NN + k0) >> 1;   // u32 index
        ((u32*)g_m2B)[ob + lane] = pkh2(__float2half_rn(v0), __float2half_rn(v1));
        ((u32*)g_m2A)[ob + lane] =
            pkh2(__float2half_rn(v0 * dv.x), __float2half_rn(v1 * dv.y));
    }
}

// =====================  fp16 1-term tensor-core GEMM, SYMMETRIC (triangular tiles)  ========
// M = A*B; which==0: adjAv fp32 (diag=1); which==1: adjAe fp16 scaled (diag=DV_SCALE) + colmax
#define KB 64
#define STG_BYTES 32768          // A 16K | B 16K
#define TP 129                   // transpose pitch (floats)
#define SMEM_DYN (128 * TP * 4 + 512)   // 66560 > 2*STG_BYTES = 65536

__device__ __forceinline__ void stage_load(u32 st0, int s,
        const __half* __restrict__ A, const __half* __restrict__ B,
        int K, int m0, int n0, int k0, int tid) {
    u32 base = st0 + s * STG_BYTES;
#pragma unroll
    for (int i = 0; i < 8; i++) {
        int id = tid + i * 128;                // 0..1023
        int r = id >> 3, c = id & 7;           // 128 rows x 8 16B-chunks
        u32 so = (u32)(r * 128 + ((c ^ (r & 7)) << 4));
        cp16(base + so, A + (size_t)(m0 + r) * K + k0 + c * 8);
        cp16(base + 16384 + so, B + (size_t)(n0 + r) * K + k0 + c * 8);
    }
    asm volatile("cp.async.commit_group;" ::: "memory");
}

__global__ __launch_bounds__(128, 2) void k_mult_mma(int which, const float* __restrict__ adj) {
    extern __shared__ char smem[];
    const __half *A, *B;
    int K, ncols;
    if (which == 0) { A = g_m1A; B = g_m1B; K = NE; ncols = NN; }
    else            { A = g_m2A; B = g_m2B; K = NN; ncols = NE; }
    // triangular tile decode: t -> (bi >= bj)
    const int t = blockIdx.x;
    int bi = (int)((sqrtf(8.0f * (float)t + 1.0f) - 1.0f) * 0.5f);
    while ((bi + 1) * (bi + 2) / 2 <= t) bi++;
    while (bi * (bi + 1) / 2 > t) bi--;
    const int bj = t - bi * (bi + 1) / 2;
    const int m0 = bi * 128, n0 = bj * 128;
    const bool diagtile = (bi == bj);

    const u32 st0 = smem_u32(smem);
    const int tid = threadIdx.x;
    const int lane = tid & 31, wid = tid >> 5;
    const int wm = wid >> 1, wn = wid & 1;          // 2 x 2 warp grid, 64x64 tiles
    const int nk = K / KB;

    float acc[4][8][4];
#pragma unroll
    for (int i = 0; i < 4; i++)
#pragma unroll
        for (int j = 0; j < 8; j++)
#pragma unroll
            for (int q = 0; q < 4; q++) acc[i][j][q] = 0.f;

    stage_load(st0, 0, A, B, K, m0, n0, 0, tid);
    stage_load(st0, 1, A, B, K, m0, n0, KB, tid);

    const u32 arow = (u32)(wm * 64 + (lane & 15));
    const u32 brow = (u32)(wn * 64 + (lane & 15));
    const u32 asw = arow & 7, bsw = brow & 7;

    for (int kt = 0; kt < nk; kt++) {
        const int s = kt & 1;
        if (kt + 1 < nk) asm volatile("cp.async.wait_group 1;" ::: "memory");
        else             asm volatile("cp.async.wait_group 0;" ::: "memory");
        __syncthreads();

        const u32 base = st0 + s * STG_BYTES;
#pragma unroll
        for (int ks = 0; ks < 4; ks++) {
            const u32 cb = (u32)(ks * 2) + (u32)(lane >> 4);
            u32 Bh[8][2], Ah[4][4];
            const u32 boff = base + 16384 + brow * 128 + ((cb ^ bsw) << 4);
#pragma unroll
            for (int nip = 0; nip < 4; nip++) {
                u32 tr[4];
                LDSM4(tr, boff + nip * 2048);
                Bh[2 * nip][0] = tr[0]; Bh[2 * nip][1] = tr[2];
                Bh[2 * nip + 1][0] = tr[1]; Bh[2 * nip + 1][1] = tr[3];
            }
            const u32 aoff = base + arow * 128 + ((cb ^ asw) << 4);
#pragma unroll
            for (int mi = 0; mi < 4; mi++)
                LDSM4(Ah[mi], aoff + mi * 2048);
#pragma unroll
            for (int mi = 0; mi < 4; mi++)
#pragma unroll
                for (int ni = 0; ni < 8; ni++)
                    MMA_F16(acc[mi][ni], Ah[mi], Bh[ni]);
        }
        __syncthreads();
        if (kt + 2 < nk)
            stage_load(st0, s, A, B, K, m0, n0, (kt + 2) * KB, tid);
    }

    // ---------- epilogue ----------
    float* stg = (float*)smem;                         // 128 x TP floats (transpose staging)
    u32* scm = (u32*)(smem + 128 * TP * 4);            // 128 u32 colmax (direct block)
    if (which == 1 && tid < 128) scm[tid] = 0u;
    __syncthreads();

    u32 kmax[8][2];
#pragma unroll
    for (int ni = 0; ni < 8; ni++) { kmax[ni][0] = 0u; kmax[ni][1] = 0u; }

    const float dval = (which == 0) ? 1.0f : DV_SCALE;   // diag value (scaled for adjAe)

#pragma unroll
    for (int mi = 0; mi < 4; mi++) {
#pragma unroll
        for (int h = 0; h < 2; h++) {
            const int row_l = wm * 64 + mi * 16 + (lane >> 2) + h * 8;
            const int row_g = m0 + row_l;
            const size_t rb = (size_t)row_g * ncols;
#pragma unroll
            for (int ni = 0; ni < 8; ni++) {
                const int col_l = wn * 64 + ni * 8 + (lane & 3) * 2;
                const int col_g = n0 + col_l;
                float v0 = acc[mi][ni][h * 2];
                float v1 = acc[mi][ni][h * 2 + 1];
                if (diagtile) {
                    if (row_g == col_g) v0 = dval;
                    if (row_g == col_g + 1) v1 = dval;
                } else {
                    stg[row_l * TP + col_l] = v0;
                    stg[row_l * TP + col_l + 1] = v1;
                }
                const float2 a = *(const float2*)(adj + rb + col_g);
                float w0 = v0 * a.x, w1 = v1 * a.y;
                if (which == 0) {
                    *(float2*)(g_adjAv + rb + col_g) = make_float2(w0, w1);
                } else {
                    *(__half2*)(g_adjAe + rb + col_g) = __floats2half2_rn(w0, w1);
                    kmax[ni][0] = max(kmax[ni][0], fkey(w0));
                    kmax[ni][1] = max(kmax[ni][1], fkey(w1));
                }
            }
        }
    }
    if (which == 1) {
#pragma unroll
        for (int ni = 0; ni < 8; ni++) {
            const int cl = wn * 64 + ni * 8 + (lane & 3) * 2;
            atomicMax(scm + cl, kmax[ni][0]);
            atomicMax(scm + cl + 1, kmax[ni][1]);
        }
    }
    __syncthreads();
    if (which == 1 && tid < 128) atomicMax(g_cmaxu + n0 + tid, scm[tid]);

    // mirror block: C[n0+c][m0+r] = M[r][c] * adj[n0+c][m0+r]
    if (!diagtile) {
        u32 kloc[4] = {0u, 0u, 0u, 0u};
        for (int cc = 0; cc < 32; cc++) {
            const int c = wid * 32 + cc;
            const size_t orow = (size_t)(n0 + c) * ncols + m0;
#pragma unroll
            for (int ch = 0; ch < 4; ch++) {
                const int r = ch * 32 + lane;
                float v = stg[r * TP + c];
                float w = v * adj[orow + r];
                if (which == 0) {
                    g_adjAv[orow + r] = w;
                } else {
                    g_adjAe[orow + r] = __float2half_rn(w);
                    kloc[ch] = max(kloc[ch], fkey(w));
                }
            }
        }
        if (which == 1) {
#pragma unroll
            for (int ch = 0; ch < 4; ch++)
                atomicMax(g_cmaxu + m0 + ch * 32 + lane, kloc[ch]);
        }
    }
}

// =====================  Hv partials: g_hvp[kc] = adjAv[:, kc*512:(kc+1)*512] @ HW  ======
__global__ __launch_bounds__(256) void k_hv(float* __restrict__ dummy) {
    __shared__ __align__(16) float As[32 * 32];
    __shared__ __align__(16) float Bs[32 * 64];
    const int tid = threadIdx.x;
    const int tx = tid & 15, ty = tid >> 4;
    const int m0 = blockIdx.x * 32;
    const int kc = blockIdx.y;
    const int arow = tid >> 3, ac4 = (tid & 7) * 4;
    const int brow = tid >> 4, bc4 = (tid & 15) * 4;
    float acc[2][4] = {{0, 0, 0, 0}, {0, 0, 0, 0}};
    for (int k0 = kc * 512; k0 < (kc + 1) * 512; k0 += 32) {
        float4 fa = *(const float4*)(g_adjAv + (m0 + arow) * NN + k0 + ac4);
        float4 fb0 = *(const float4*)(g_HW + (k0 + brow) * DVO + bc4);
        float4 fb1 = *(const float4*)(g_HW + (k0 + brow + 16) * DVO + bc4);
        __syncthreads();
        As[(ac4 + 0) * 32 + arow] = fa.x; As[(ac4 + 1) * 32 + arow] = fa.y;
        As[(ac4 + 2) * 32 + arow] = fa.z; As[(ac4 + 3) * 32 + arow] = fa.w;
        *(float4*)(Bs + brow * 64 + bc4) = fb0;
        *(float4*)(Bs + (brow + 16) * 64 + bc4) = fb1;
        __syncthreads();
#pragma unroll
        for (int kk = 0; kk < 32; kk++) {
            float a0 = As[kk * 32 + ty * 2];
            float a1 = As[kk * 32 + ty * 2 + 1];
            float4 b = *(const float4*)(Bs + kk * 64 + tx * 4);
            acc[0][0] += a0 * b.x; acc[0][1] += a0 * b.y; acc[0][2] += a0 * b.z; acc[0][3] += a0 * b.w;
            acc[1][0] += a1 * b.x; acc[1][1] += a1 * b.y; acc[1][2] += a1 * b.z; acc[1][3] += a1 * b.w;
        }
    }
#pragma unroll
    for (int r = 0; r < 2; r++) {
        int row = m0 + ty * 2 + r;
        *(float4*)(g_hvp[kc] + row * DVO + tx * 4) =
            make_float4(acc[r][0], acc[r][1], acc[r][2], acc[r][3]);
    }
}

// reduce Hv partials + bias -> out; fused d_v = Hv_out . p_e (one warp per row)
__global__ void k_hvdv(const float* __restrict__ bv, const float* __restrict__ pe,
                       float* __restrict__ out) {
    int w = (blockIdx.x * 256 + threadIdx.x) >> 5;     // row 0..2047
    int lane = threadIdx.x & 31;
    int i0 = w * DVO + lane, i1 = i0 + 32;
    float s0 = bv[lane] + g_hvp[0][i0] + g_hvp[1][i0] + g_hvp[2][i0] + g_hvp[3][i0];
    float s1 = bv[lane + 32] + g_hvp[0][i1] + g_hvp[1][i1] + g_hvp[2][i1] + g_hvp[3][i1];
    out[i0] = s0; out[i1] = s1;
    float d = s0 * pe[lane] + s1 * pe[lane + 32];
#pragma unroll
    for (int o = 16; o > 0; o >>= 1) d += __shfl_down_sync(0xffffffffu, d, o);
    if (lane == 0) g_dv[w] = d;
}

// finalize colmax; emit HeWsT[c][n] = fp16(HeW[n][c] / (colmax_s + 1e-10) * 2^12)
__global__ void k_cmax2() {
    int col = blockIdx.x * 256 + threadIdx.x;
    u32 k = g_cmaxu[col];
    u32 b = (k & 0x80000000u) ? (k ^ 0x80000000u) : ~k;
    float m = __uint_as_float(b);
    float inv = HE_SCALE / (m + 1e-10f);
#pragma unroll
    for (int c = 0; c < DEO; c++)
        g_HeWsT[c * NE + col] = __float2half_rn(g_HeW[col * DEO + c] * inv);
}

// =====================  He partials via tensor cores: g_hep[kc] = adjAe_chunk @ HeWsT  ====
#define HE_KB 64
#define HE_STG 18432             // A 16K (128x128B) | B 2K (16x128B)
__global__ __launch_bounds__(128, 2) void k_he_mma() {
    __shared__ __align__(1024) char smem[2 * HE_STG];
    const u32 st0 = smem_u32(smem);
    const int tid = threadIdx.x;
    const int lane = tid & 31, w = tid >> 5;         // 4 warps, 32 rows each
    const int m0 = blockIdx.x * 128;
    const int kc = blockIdx.y;
    const int kbase = kc * (NE / 4);                 // 1536-wide K slice
    const int nk = (NE / 4) / HE_KB;                 // 24

    float acc[2][2][4];
#pragma unroll
    for (int i = 0; i < 2; i++)
#pragma unroll
        for (int j = 0; j < 2; j++)
#pragma unroll
            for (int q = 0; q < 4; q++) acc[i][j][q] = 0.f;

    // stage loader: A rows 128 x 64 halfs; B rows 16 x 64 halfs
    auto load = [&](int s, int k0) {
        u32 base = st0 + s * HE_STG;
#pragma unroll
        for (int i = 0; i < 8; i++) {
            int id = tid + i * 128;
            int r = id >> 3, c = id & 7;
            u32 so = (u32)(r * 128 + ((c ^ (r & 7)) << 4));
            cp16(base + so, g_adjAe + (size_t)(m0 + r) * NE + kbase + k0 + c * 8);
        }
        {
            int r = tid >> 3, c = tid & 7;           // 16 rows x 8 chunks = 128
            u32 so = (u32)(r * 128 + ((c ^ (r & 7)) << 4));
            cp16(base + 16384 + so, g_HeWsT + (size_t)r * NE + kbase + k0 + c * 8);
        }
        asm volatile("cp.async.commit_group;" ::: "memory");
    };

    load(0, 0);
    load(1, HE_KB);

    const u32 arow = (u32)(w * 32 + (lane & 15));
    const u32 brow = (u32)(lane & 15);
    const u32 asw = arow & 7, bsw = brow & 7;

    for (int kt = 0; kt < nk; kt++) {
        const int s = kt & 1;
        if (kt + 1 < nk) asm volatile("cp.async.wait_group 1;" ::: "memory");
        else             asm volatile("cp.async.wait_group 0;" ::: "memory");
        __syncthreads();
        const u32 base = st0 + s * HE_STG;
#pragma unroll
        for (int ks = 0; ks < 4; ks++) {
            const u32 cb = (u32)(ks * 2) + (u32)(lane >> 4);
            u32 Bf[2][2], Af[2][4];
            {
                u32 tr[4];
                LDSM4(tr, base + 16384 + brow * 128 + ((cb ^ bsw) << 4));
                Bf[0][0] = tr[0]; Bf[0][1] = tr[2];
                Bf[1][0] = tr[1]; Bf[1][1] = tr[3];
            }
            const u32 aoff = base + arow * 128 + ((cb ^ asw) << 4);
            LDSM4(Af[0], aoff);
            LDSM4(Af[1], aoff + 2048);
#pragma unroll
            for (int mi = 0; mi < 2; mi++)
#pragma unroll
                for (int ni = 0; ni < 2; ni++)
                    MMA_F16(acc[mi][ni], Af[mi], Bf[ni]);
        }
        __syncthreads();
        if (kt + 2 < nk) load(s, (kt + 2) * HE_KB);
    }

    // write partials
#pragma unroll
    for (int mi = 0; mi < 2; mi++)
#pragma unroll
        for (int h = 0; h < 2; h++) {
            const int row_g = m0 + w * 32 + mi * 16 + (lane >> 2) + h * 8;
#pragma unroll
            for (int ni = 0; ni < 2; ni++) {
                const int col = ni * 8 + (lane & 3) * 2;
                *(float2*)(g_hep[kc] + row_g * DEO + col) =
                    make_float2(acc[mi][ni][h * 2], acc[mi][ni][h * 2 + 1]);
            }
        }
}

// reduce He partials, unscale, + bias -> out
__global__ void k_hered(const float* __restrict__ be, float* __restrict__ out) {
    int idx = blockIdx.x * 256 + threadIdx.x;          // 98304
    int c = idx & 15;
    float s = (g_hep[0][idx] + g_hep[1][idx] + g_hep[2][idx] + g_hep[3][idx]) * HE_UNSCALE
              + be[c];
    out[idx] = s;
}

// =====================  launch  =====================
extern "C" void kernel_launch(void* const* d_in, const int* in_sizes, int n_in,
                              void* d_out, int out_size) {
    const float* H_v  = (const float*)d_in[0];
    const float* H_e  = (const float*)d_in[1];
    const float* adjv = (const float*)d_in[2];
    const float* adje = (const float*)d_in[3];
    const float* T    = (const float*)d_in[4];
    const float* W_v  = (const float*)d_in[5];
    const float* b_v  = (const float*)d_in[6];
    const float* p_v  = (const float*)d_in[7];
    const float* W_e  = (const float*)d_in[8];
    const float* b_e  = (const float*)d_in[9];
    const float* p_e  = (const float*)d_in[10];
    float* out = (float*)d_out;
    (void)in_sizes; (void)n_in; (void)out_size;

    cudaFuncSetAttribute(k_mult_mma, cudaFuncAttributeMaxDynamicSharedMemorySize, SMEM_DYN);

    k_de<<<24, 256>>>(H_e, p_v);                    // d_e + colmax init
    k_hew<<<384, 256>>>(H_e, W_e);
    k_hw<<<512, 256>>>(H_v, W_v);
    k_split1<<<12288, 256>>>(T);
    k_mult_mma<<<136, 128, SMEM_DYN>>>(0, adjv);    // adjAv fp32, triangular
    k_hv<<<dim3(64, 4), 256>>>(out);                // split-K partials
    k_hvdv<<<256, 256>>>(b_v, p_e, out);            // reduce + bias + d_v
    k_split2<<<dim3(192, 32), dim3(32, 8)>>>(T);
    k_mult_mma<<<1176, 128, SMEM_DYN>>>(1, adje);   // adjAe fp16 scaled + colmax
    k_cmax2<<<24, 256>>>();                         // colmax -> HeWsT fp16
    k_he_mma<<<dim3(48, 4), 128>>>();               // He partials on tensor cores
    k_hered<<<384, 256>>>(b_e, out + NN * DVO);     // reduce + unscale + bias
}